// round 1
// baseline (speedup 1.0000x reference)
#include <cuda_runtime.h>
#include <cstdint>
#include <cstddef>

#define HD 1024
#define NB 128
#define NS 128
#define NROW (NB*NS)
#define LDK 36
#define NCTA_SCAN 128

// ---------------- scratch (device globals: allocation-free) ----------------
__device__ __align__(16) float g_FR[(size_t)NS*NB*HD];     // [s][b][h]  64 MB
__device__ __align__(16) float g_FW[(size_t)NS*NB*HD];     // [s][b][h]  64 MB
__device__ __align__(16) float g_C[NB*HD];                 // GRU state
__device__ __align__(16) float g_Otmp[NB*HD];              // split-K accum for final GEMM
__device__ __align__(16) float g_part[(size_t)NCTA_SCAN*128*128]; // scan partials, 8 MB
__device__ __align__(16) float g_Glogit[NROW];             // [b*S+s]
__device__ __align__(16) float g_Gt[NS*NB];                // softmax(G) transposed [s][b]
__device__ unsigned g_barctr;

// ---------------- tf32 mma helpers ----------------
__device__ __forceinline__ unsigned f2tf(float f){
    unsigned u; asm("cvt.rna.tf32.f32 %0, %1;" : "=r"(u) : "f"(f)); return u;
}
__device__ __forceinline__ void mma8(float* d, const unsigned* a, const unsigned* b){
    asm volatile("mma.sync.aligned.m16n8k8.row.col.f32.tf32.tf32.f32 "
        "{%0,%1,%2,%3},{%4,%5,%6,%7},{%8,%9},{%0,%1,%2,%3};\n"
        : "+f"(d[0]),"+f"(d[1]),"+f"(d[2]),"+f"(d[3])
        : "r"(a[0]),"r"(a[1]),"r"(a[2]),"r"(a[3]),"r"(b[0]),"r"(b[1]));
}

// One K-chunk (32) of a 128x128 CTA tile. 8 warps: 4 along M (32 rows), 2 along N (64 cols).
__device__ __forceinline__ void compute_chunk(const unsigned* As, const unsigned* Bs,
        float acc[2][8][4], int warp_m, int warp_n, int lg, int lk){
    #pragma unroll
    for (int ks = 0; ks < 4; ks++){
        int k0 = ks*8 + lk;
        unsigned a[2][4], b[8][2];
        #pragma unroll
        for (int mi = 0; mi < 2; mi++){
            int m0 = warp_m + mi*16 + lg;
            a[mi][0] = As[m0*LDK + k0];
            a[mi][1] = As[(m0+8)*LDK + k0];
            a[mi][2] = As[m0*LDK + k0+4];
            a[mi][3] = As[(m0+8)*LDK + k0+4];
        }
        #pragma unroll
        for (int ni = 0; ni < 8; ni++){
            int n0 = warp_n + ni*8 + lg;
            b[ni][0] = Bs[n0*LDK + k0];
            b[ni][1] = Bs[n0*LDK + k0+4];
        }
        #pragma unroll
        for (int mi = 0; mi < 2; mi++)
            #pragma unroll
            for (int ni = 0; ni < 8; ni++)
                mma8(acc[mi][ni], a[mi], b[ni]);
    }
}

// Load a 128(n) x 32(k) weight tile from row-major [n][k] global into tf32 SMEM.
__device__ __forceinline__ void load_w_tile(unsigned* Bs, const float* __restrict__ base,
                                            int ldb, int tid){
    #pragma unroll
    for (int i = 0; i < 4; i++){
        int slot = tid + i*256;
        int n = slot >> 3, c4 = (slot & 7) * 4;
        float4 v = *reinterpret_cast<const float4*>(base + (size_t)n*ldb + c4);
        Bs[n*LDK + c4+0] = f2tf(v.x);
        Bs[n*LDK + c4+1] = f2tf(v.y);
        Bs[n*LDK + c4+2] = f2tf(v.z);
        Bs[n*LDK + c4+3] = f2tf(v.w);
    }
}

#define ZERO_ACC(acc) { \
    _Pragma("unroll") for (int _i=0;_i<2;_i++) \
    _Pragma("unroll") for (int _j=0;_j<8;_j++) \
    _Pragma("unroll") for (int _k=0;_k<4;_k++) acc[_i][_j][_k]=0.f; }

// ---------------- K0: per-replay init ----------------
__global__ void k_init(){
    int i = blockIdx.x * blockDim.x + threadIdx.x;
    if (i == 0) g_barctr = 0u;
    if (i < NROW) g_Glogit[i] = 0.f;
    if (i < NB*HD){ g_C[i] = 0.f; g_Otmp[i] = 0.f; }
}

// ---------------- K1: G logits ----------------
// logit[b,s] = sum_h tanh( sum_j z[b,s,j]*Wz1[h,j] + bz1[h] ) * Wz2[h]
// z built on the fly from facts/q/m; epilogue fuses tanh * Wz2 reduction -> atomicAdd.
__global__ void k_gemm_G(const float* __restrict__ facts, const float* __restrict__ q,
                         const float* __restrict__ pm, const float* __restrict__ Wz1,
                         const float* __restrict__ bz1, const float* __restrict__ Wz2){
    __shared__ unsigned As[128*LDK];
    __shared__ unsigned Bs[128*LDK];
    int bt = blockIdx.y, nt = blockIdx.x;
    int tid = threadIdx.x, wid = tid >> 5, lane = tid & 31, lg = lane >> 2, lk = lane & 3;
    int warp_m = (wid >> 1) * 32, warp_n = (wid & 1) * 64;
    float acc[2][8][4]; ZERO_ACC(acc);

    const float* fb = facts + (size_t)bt*NS*HD;
    const float* qb = q  + (size_t)bt*HD;
    const float* mb = pm + (size_t)bt*HD;

    for (int kc = 0; kc < 4*HD; kc += 32){
        int part = kc >> 10;
        int jj = kc & (HD-1);
        #pragma unroll
        for (int i = 0; i < 4; i++){
            int slot = tid + i*256;
            int s = slot >> 3, c4 = (slot & 7) * 4;
            float4 f  = *reinterpret_cast<const float4*>(fb + (size_t)s*HD + jj + c4);
            float4 qv = *reinterpret_cast<const float4*>(qb + jj + c4);
            float4 mv = *reinterpret_cast<const float4*>(mb + jj + c4);
            float4 z;
            if (part == 0){      z.x=f.x*qv.x; z.y=f.y*qv.y; z.z=f.z*qv.z; z.w=f.w*qv.w; }
            else if (part == 1){ z.x=f.x*mv.x; z.y=f.y*mv.y; z.z=f.z*mv.z; z.w=f.w*mv.w; }
            else if (part == 2){ z.x=fabsf(f.x-qv.x); z.y=fabsf(f.y-qv.y); z.z=fabsf(f.z-qv.z); z.w=fabsf(f.w-qv.w); }
            else {               z.x=fabsf(f.x-mv.x); z.y=fabsf(f.y-mv.y); z.z=fabsf(f.z-mv.z); z.w=fabsf(f.w-mv.w); }
            As[s*LDK + c4+0] = f2tf(z.x);
            As[s*LDK + c4+1] = f2tf(z.y);
            As[s*LDK + c4+2] = f2tf(z.z);
            As[s*LDK + c4+3] = f2tf(z.w);
        }
        load_w_tile(Bs, Wz1 + (size_t)(nt*128)*(4*HD) + kc, 4*HD, tid);
        __syncthreads();
        compute_chunk(As, Bs, acc, warp_m, warp_n, lg, lk);
        __syncthreads();
    }

    // epilogue: tanh, * Wz2[h], reduce over this CTA's 128 columns
    float rs[4] = {0.f, 0.f, 0.f, 0.f};
    #pragma unroll
    for (int mi = 0; mi < 2; mi++)
        #pragma unroll
        for (int ni = 0; ni < 8; ni++){
            int c0 = nt*128 + warp_n + ni*8 + lk*2;
            float w0 = Wz2[c0], w1 = Wz2[c0+1];
            float z0 = bz1[c0], z1 = bz1[c0+1];
            rs[mi*2+0] += tanhf(acc[mi][ni][0]+z0)*w0 + tanhf(acc[mi][ni][1]+z1)*w1;
            rs[mi*2+1] += tanhf(acc[mi][ni][2]+z0)*w0 + tanhf(acc[mi][ni][3]+z1)*w1;
        }
    #pragma unroll
    for (int r = 0; r < 4; r++){
        rs[r] += __shfl_xor_sync(0xffffffffu, rs[r], 1);
        rs[r] += __shfl_xor_sync(0xffffffffu, rs[r], 2);
    }
    if (lk == 0){
        int s0 = warp_m + lg;
        atomicAdd(&g_Glogit[bt*NS + s0     ], rs[0]);
        atomicAdd(&g_Glogit[bt*NS + s0 + 8 ], rs[1]);
        atomicAdd(&g_Glogit[bt*NS + s0 + 16], rs[2]);
        atomicAdd(&g_Glogit[bt*NS + s0 + 24], rs[3]);
    }
}

// ---------------- K2: softmax over S per batch, store transposed [s][b] ----------------
__global__ void k_softmax(){
    int bt = blockIdx.x, t = threadIdx.x;   // 128 threads
    float v = g_Glogit[bt*NS + t];
    __shared__ float sm[4], ss[4];
    float mx = v;
    #pragma unroll
    for (int o = 16; o; o >>= 1) mx = fmaxf(mx, __shfl_xor_sync(0xffffffffu, mx, o));
    if ((t & 31) == 0) sm[t >> 5] = mx;
    __syncthreads();
    mx = fmaxf(fmaxf(sm[0], sm[1]), fmaxf(sm[2], sm[3]));
    float e = __expf(v - mx);
    float sum = e;
    #pragma unroll
    for (int o = 16; o; o >>= 1) sum += __shfl_xor_sync(0xffffffffu, sum, o);
    if ((t & 31) == 0) ss[t >> 5] = sum;
    __syncthreads();
    sum = ss[0] + ss[1] + ss[2] + ss[3];
    g_Gt[t*NB + bt] = e / sum;
}

// ---------------- K3: FR = facts@Wr^T+br ; FW = facts@W^T+bw, stored [s][b][h] ----------------
__global__ void k_gemm_F(const float* __restrict__ facts,
                         const float* __restrict__ Wr, const float* __restrict__ br,
                         const float* __restrict__ W,  const float* __restrict__ bw){
    __shared__ unsigned As[128*LDK];
    __shared__ unsigned Bs[128*LDK];
    int bt = blockIdx.y, nt = blockIdx.x, which = blockIdx.z;
    const float* Wsel = which ? W  : Wr;
    const float* bsel = which ? bw : br;
    float* Out = which ? g_FW : g_FR;
    int tid = threadIdx.x, wid = tid >> 5, lane = tid & 31, lg = lane >> 2, lk = lane & 3;
    int warp_m = (wid >> 1) * 32, warp_n = (wid & 1) * 64;
    float acc[2][8][4]; ZERO_ACC(acc);
    const float* fb = facts + (size_t)bt*NS*HD;

    for (int kc = 0; kc < HD; kc += 32){
        #pragma unroll
        for (int i = 0; i < 4; i++){
            int slot = tid + i*256;
            int s = slot >> 3, c4 = (slot & 7) * 4;
            float4 f = *reinterpret_cast<const float4*>(fb + (size_t)s*HD + kc + c4);
            As[s*LDK + c4+0] = f2tf(f.x);
            As[s*LDK + c4+1] = f2tf(f.y);
            As[s*LDK + c4+2] = f2tf(f.z);
            As[s*LDK + c4+3] = f2tf(f.w);
        }
        load_w_tile(Bs, Wsel + (size_t)(nt*128)*HD + kc, HD, tid);
        __syncthreads();
        compute_chunk(As, Bs, acc, warp_m, warp_n, lg, lk);
        __syncthreads();
    }
    #pragma unroll
    for (int mi = 0; mi < 2; mi++){
        int r0 = warp_m + mi*16 + lg;  // r0 == s index
        #pragma unroll
        for (int ni = 0; ni < 8; ni++){
            int h = nt*128 + warp_n + ni*8 + lk*2;
            float b0 = bsel[h], b1 = bsel[h+1];
            float2 v0 = make_float2(acc[mi][ni][0]+b0, acc[mi][ni][1]+b1);
            float2 v1 = make_float2(acc[mi][ni][2]+b0, acc[mi][ni][3]+b1);
            *reinterpret_cast<float2*>(Out + (size_t)r0*(NB*HD) + (size_t)bt*HD + h) = v0;
            *reinterpret_cast<float2*>(Out + (size_t)(r0+8)*(NB*HD) + (size_t)bt*HD + h) = v1;
        }
    }
}

// ---------------- K4: persistent scan, 128 steps ----------------
__device__ __forceinline__ void grid_sync(unsigned &target){
    __syncthreads();
    if (threadIdx.x == 0){
        __threadfence();
        atomicAdd(&g_barctr, 1u);
        target += NCTA_SCAN;
        while (atomicAdd(&g_barctr, 0u) < target) { __nanosleep(32); }
    }
    __syncthreads();
}

__device__ __forceinline__ float gru_upd(float fr, float fw, float y1, float y2,
                                         float b_ur, float b_u, float c, float g){
    float r  = 1.f / (1.f + __expf(-(fr + y1 + b_ur)));
    float ht = tanhf(fw + r * (y2 + b_u));
    return g * ht + (1.f - g) * c;
}

__global__ void k_scan(const float* __restrict__ Ur, const float* __restrict__ bur,
                       const float* __restrict__ U,  const float* __restrict__ bu){
    __shared__ unsigned As[128*LDK];
    __shared__ unsigned Bs[128*LDK];
    int cta = blockIdx.x, tid = threadIdx.x;
    int wid = tid >> 5, lane = tid & 31, lg = lane >> 2, lk = lane & 3;
    int warp_m = (wid >> 1) * 32, warp_n = (wid & 1) * 64;
    int nt = cta >> 3;              // 0..15: 0-7 -> Y1 (Ur), 8-15 -> Y2 (U)
    int kcb = (cta & 7) * 128;      // K slice
    const float* Wsel = (nt < 8) ? Ur : U;
    int nbase = (nt & 7) * 128;
    float* P = g_part + (size_t)cta * 16384;

    // phase-B element ownership (4 consecutive elements of C per thread)
    int e  = (cta*256 + tid) * 4;
    int eb = e >> 10, eh = e & (HD-1);
    int nt1 = eh >> 7, hm = eh & 127;

    unsigned target = 0;
    for (int s = 0; s < NS; s++){
        // ---- phase A: partial GEMM  P = C[:,kslice] @ Wsel[ntile,kslice]^T
        float acc[2][8][4]; ZERO_ACC(acc);
        for (int kc = 0; kc < 128; kc += 32){
            #pragma unroll
            for (int i = 0; i < 4; i++){
                int slot = tid + i*256;
                int bb = slot >> 3, c4 = (slot & 7) * 4;
                float4 v = __ldcg(reinterpret_cast<const float4*>(g_C + (size_t)bb*HD + kcb + kc + c4));
                As[bb*LDK + c4+0] = f2tf(v.x);
                As[bb*LDK + c4+1] = f2tf(v.y);
                As[bb*LDK + c4+2] = f2tf(v.z);
                As[bb*LDK + c4+3] = f2tf(v.w);
            }
            load_w_tile(Bs, Wsel + (size_t)nbase*HD + kcb + kc, HD, tid);
            __syncthreads();
            compute_chunk(As, Bs, acc, warp_m, warp_n, lg, lk);
            __syncthreads();
        }
        #pragma unroll
        for (int mi = 0; mi < 2; mi++){
            int r0 = warp_m + mi*16 + lg;
            #pragma unroll
            for (int ni = 0; ni < 8; ni++){
                int c = warp_n + ni*8 + lk*2;
                __stcg(reinterpret_cast<float2*>(P + r0*128 + c),
                       make_float2(acc[mi][ni][0], acc[mi][ni][1]));
                __stcg(reinterpret_cast<float2*>(P + (r0+8)*128 + c),
                       make_float2(acc[mi][ni][2], acc[mi][ni][3]));
            }
        }
        grid_sync(target);

        // ---- phase B: reduce partials, GRU update of C
        float4 y1 = make_float4(0,0,0,0), y2 = make_float4(0,0,0,0);
        #pragma unroll
        for (int kk = 0; kk < 8; kk++){
            float4 p1 = __ldcg(reinterpret_cast<const float4*>(
                g_part + (size_t)(nt1*8 + kk)*16384 + eb*128 + hm));
            float4 p2 = __ldcg(reinterpret_cast<const float4*>(
                g_part + (size_t)((nt1+8)*8 + kk)*16384 + eb*128 + hm));
            y1.x += p1.x; y1.y += p1.y; y1.z += p1.z; y1.w += p1.w;
            y2.x += p2.x; y2.y += p2.y; y2.z += p2.z; y2.w += p2.w;
        }
        float4 fr = *reinterpret_cast<const float4*>(g_FR + (size_t)s*NB*HD + (size_t)eb*HD + eh);
        float4 fw = *reinterpret_cast<const float4*>(g_FW + (size_t)s*NB*HD + (size_t)eb*HD + eh);
        float4 co = __ldcg(reinterpret_cast<const float4*>(g_C + (size_t)eb*HD + eh));
        float4 vur = *reinterpret_cast<const float4*>(bur + eh);
        float4 vu  = *reinterpret_cast<const float4*>(bu + eh);
        float gg = g_Gt[s*NB + eb];
        float4 cn;
        cn.x = gru_upd(fr.x, fw.x, y1.x, y2.x, vur.x, vu.x, co.x, gg);
        cn.y = gru_upd(fr.y, fw.y, y1.y, y2.y, vur.y, vu.y, co.y, gg);
        cn.z = gru_upd(fr.z, fw.z, y1.z, y2.z, vur.z, vu.z, co.z, gg);
        cn.w = gru_upd(fr.w, fw.w, y1.w, y2.w, vur.w, vu.w, co.w, gg);
        __stcg(reinterpret_cast<float4*>(g_C + (size_t)eb*HD + eh), cn);
        grid_sync(target);
    }
}

// ---------------- K5: final GEMM (split-K, atomic accumulate) ----------------
__global__ void k_out(const float* __restrict__ pm, const float* __restrict__ q,
                      const float* __restrict__ Wm){
    __shared__ unsigned As[128*LDK];
    __shared__ unsigned Bs[128*LDK];
    int nt = blockIdx.x;            // 0..7 (N tile)
    int ks = blockIdx.y;            // 0..11 (K split, 256 each)
    int kbase = ks * 256;
    int tid = threadIdx.x, wid = tid >> 5, lane = tid & 31, lg = lane >> 2, lk = lane & 3;
    int warp_m = (wid >> 1) * 32, warp_n = (wid & 1) * 64;
    float acc[2][8][4]; ZERO_ACC(acc);

    for (int kc = 0; kc < 256; kc += 32){
        int kg = kbase + kc;
        int seg = kg >> 10;
        int jj = kg & (HD-1);
        #pragma unroll
        for (int i = 0; i < 4; i++){
            int slot = tid + i*256;
            int bb = slot >> 3, c4 = (slot & 7) * 4;
            float4 v;
            if (seg == 0)      v = *reinterpret_cast<const float4*>(pm + (size_t)bb*HD + jj + c4);
            else if (seg == 1) v = __ldcg(reinterpret_cast<const float4*>(g_C + (size_t)bb*HD + jj + c4));
            else               v = *reinterpret_cast<const float4*>(q + (size_t)bb*HD + jj + c4);
            As[bb*LDK + c4+0] = f2tf(v.x);
            As[bb*LDK + c4+1] = f2tf(v.y);
            As[bb*LDK + c4+2] = f2tf(v.z);
            As[bb*LDK + c4+3] = f2tf(v.w);
        }
        load_w_tile(Bs, Wm + (size_t)(nt*128)*(3*HD) + kg, 3*HD, tid);
        __syncthreads();
        compute_chunk(As, Bs, acc, warp_m, warp_n, lg, lk);
        __syncthreads();
    }
    #pragma unroll
    for (int mi = 0; mi < 2; mi++){
        int r0 = warp_m + mi*16 + lg;  // batch index
        #pragma unroll
        for (int ni = 0; ni < 8; ni++){
            int h = nt*128 + warp_n + ni*8 + lk*2;
            atomicAdd(&g_Otmp[(size_t)r0*HD + h     ], acc[mi][ni][0]);
            atomicAdd(&g_Otmp[(size_t)r0*HD + h + 1 ], acc[mi][ni][1]);
            atomicAdd(&g_Otmp[(size_t)(r0+8)*HD + h    ], acc[mi][ni][2]);
            atomicAdd(&g_Otmp[(size_t)(r0+8)*HD + h + 1], acc[mi][ni][3]);
        }
    }
}

// ---------------- K6: bias + relu -> output ----------------
__global__ void k_finish(const float* __restrict__ bm, float* __restrict__ out){
    int i = blockIdx.x * blockDim.x + threadIdx.x;
    if (i < NB*HD){
        float v = g_Otmp[i] + bm[i & (HD-1)];
        out[i] = fmaxf(v, 0.f);
    }
}

// ---------------- launch ----------------
extern "C" void kernel_launch(void* const* d_in, const int* in_sizes, int n_in,
                              void* d_out, int out_size){
    (void)in_sizes; (void)n_in; (void)out_size;
    const float* facts     = (const float*)d_in[0];
    const float* questions = (const float*)d_in[1];
    const float* prevM     = (const float*)d_in[2];
    const float* Wr  = (const float*)d_in[3];
    const float* br  = (const float*)d_in[4];
    const float* Ur  = (const float*)d_in[5];
    const float* bur = (const float*)d_in[6];
    const float* W   = (const float*)d_in[7];
    const float* bw  = (const float*)d_in[8];
    const float* U   = (const float*)d_in[9];
    const float* bu  = (const float*)d_in[10];
    const float* Wz1 = (const float*)d_in[11];
    const float* bz1 = (const float*)d_in[12];
    const float* Wz2 = (const float*)d_in[13];
    // d_in[14] = bz2: softmax is shift-invariant, so it cancels exactly.
    const float* Wm  = (const float*)d_in[15];
    const float* bm  = (const float*)d_in[16];
    float* out = (float*)d_out;

    k_init<<<512, 256>>>();
    dim3 gG(8, 128);
    k_gemm_G<<<gG, 256>>>(facts, questions, prevM, Wz1, bz1, Wz2);
    k_softmax<<<128, 128>>>();
    dim3 gF(8, 128, 2);
    k_gemm_F<<<gF, 256>>>(facts, Wr, br, W, bw);
    k_scan<<<NCTA_SCAN, 256>>>(Ur, bur, U, bu);
    dim3 gO(8, 12);
    k_out<<<gO, 256>>>(prevM, questions, Wm);
    k_finish<<<512, 256>>>(bm, out);
}

// round 3
// speedup vs baseline: 1.1025x; 1.1025x over previous
#include <cuda_runtime.h>
#include <cstdint>
#include <cstddef>

#define HD 1024
#define NB 128
#define NS 128
#define NROW (NB*NS)
#define LDK 36
#define CH (128*36)          // uints per 128x32 sub-chunk tile
#define NCTA_SCAN 128
#define DYN_SMEM (8*CH*4)    // 147456 bytes

// ---------------- scratch (device globals: allocation-free) ----------------
__device__ __align__(16) float g_FR[(size_t)NS*NB*HD];     // [s][b][h]
__device__ __align__(16) float g_FW[(size_t)NS*NB*HD];     // [s][b][h]
__device__ __align__(16) float g_C[NB*HD];                 // GRU state
__device__ __align__(16) float g_Otmp[NB*HD];
__device__ __align__(16) float g_part[(size_t)NCTA_SCAN*128*128];
__device__ __align__(16) float g_Glogit[NROW];             // [b*S+s]
__device__ __align__(16) float g_Gt[NS*NB];                // softmax(G) transposed [s][b]
__device__ unsigned g_barctr;

// ---------------- helpers ----------------
__device__ __forceinline__ unsigned f2tf(float f){
    unsigned u; asm("cvt.rna.tf32.f32 %0, %1;" : "=r"(u) : "f"(f)); return u;
}
__device__ __forceinline__ uint32_t smem_u32(const void* p){
    uint32_t a; asm("{ .reg .u64 t; cvta.to.shared.u64 t, %1; cvt.u32.u64 %0, t; }"
                    : "=r"(a) : "l"(p)); return a;
}
__device__ __forceinline__ void cpa16(uint32_t dst, const void* src){
    asm volatile("cp.async.cg.shared.global [%0], [%1], 16;" :: "r"(dst), "l"(src));
}
#define CP_COMMIT() asm volatile("cp.async.commit_group;" ::: "memory")
#define CP_WAIT(n)  asm volatile("cp.async.wait_group %0;" :: "n"(n) : "memory")

__device__ __forceinline__ void mma8(float* d, const unsigned* a, const unsigned* b){
    asm volatile("mma.sync.aligned.m16n8k8.row.col.f32.tf32.tf32.f32 "
        "{%0,%1,%2,%3},{%4,%5,%6,%7},{%8,%9},{%0,%1,%2,%3};\n"
        : "+f"(d[0]),"+f"(d[1]),"+f"(d[2]),"+f"(d[3])
        : "r"(a[0]),"r"(a[1]),"r"(a[2]),"r"(a[3]),"r"(b[0]),"r"(b[1]));
}

// One k=8 step on a 128x128 tile; warp tile 32x64. k0 includes lk.
// CVTA/CVTB: operand stored raw fp32 in SMEM -> convert at fragment load.
template<int CVTA, int CVTB>
__device__ __forceinline__ void kstep8(const unsigned* __restrict__ As,
        const unsigned* __restrict__ Bs, int k0,
        float acc[2][8][4], int warp_m, int warp_n, int lg){
    unsigned a[2][4], b[8][2];
    #pragma unroll
    for (int mi = 0; mi < 2; mi++){
        int m0 = warp_m + mi*16 + lg;
        a[mi][0] = As[m0*LDK + k0];
        a[mi][1] = As[(m0+8)*LDK + k0];
        a[mi][2] = As[m0*LDK + k0+4];
        a[mi][3] = As[(m0+8)*LDK + k0+4];
        if (CVTA){
            #pragma unroll
            for (int j = 0; j < 4; j++) a[mi][j] = f2tf(__uint_as_float(a[mi][j]));
        }
    }
    #pragma unroll
    for (int ni = 0; ni < 8; ni++){
        int n0 = warp_n + ni*8 + lg;
        b[ni][0] = Bs[n0*LDK + k0];
        b[ni][1] = Bs[n0*LDK + k0+4];
        if (CVTB){
            b[ni][0] = f2tf(__uint_as_float(b[ni][0]));
            b[ni][1] = f2tf(__uint_as_float(b[ni][1]));
        }
    }
    #pragma unroll
    for (int mi = 0; mi < 2; mi++)
        #pragma unroll
        for (int ni = 0; ni < 8; ni++)
            mma8(acc[mi][ni], a[mi], b[ni]);
}

#define ZERO_ACC(acc) { \
    _Pragma("unroll") for (int _i=0;_i<2;_i++) \
    _Pragma("unroll") for (int _j=0;_j<8;_j++) \
    _Pragma("unroll") for (int _k=0;_k<4;_k++) acc[_i][_j][_k]=0.f; }

// ---------------- K0: per-replay init ----------------
__global__ void k_init(){
    int i = blockIdx.x * blockDim.x + threadIdx.x;
    if (i == 0) g_barctr = 0u;
    if (i < NROW) g_Glogit[i] = 0.f;
    if (i < NB*HD){ g_C[i] = 0.f; g_Otmp[i] = 0.f; }
}

// ================= K1: G logits (pipelined, facts 4x-reuse) =================
// CTA tile 128(s) x 128(h), K=4096 in 64 blocks of 64.
// Block kb covers z-parts {2*(kb&1), 2*(kb&1)+1} at facts cols [(kb>>1)*32, +32).
__global__ void __launch_bounds__(256,1) k2_G(
        const float* __restrict__ facts, const float* __restrict__ q,
        const float* __restrict__ pm, const float* __restrict__ Wz1,
        const float* __restrict__ bz1, const float* __restrict__ Wz2){
    extern __shared__ unsigned us[];
    uint32_t sbase = smem_u32(us);
    int tid = threadIdx.x, wid = tid >> 5, lane = tid & 31;
    int lg = lane >> 2, lk = lane & 3;
    int warp_m = (wid >> 1) * 32, warp_n = (wid & 1) * 64;
    int nt = blockIdx.x, bt = blockIdx.y;
    int c4v = (tid & 7) * 4, rb = tid >> 3;   // rb in [0,32)
    const float* fb = facts + (size_t)bt*NS*HD;
    const float* qb = q  + (size_t)bt*HD;
    const float* mb = pm + (size_t)bt*HD;

    float4 pf[4]; float4 pq, pmv;
    float acc[2][8][4]; ZERO_ACC(acc);

    // B issue for block kb into buffer buf
    #define G_ISSUE_B(kb, buf) { \
        _Pragma("unroll") for (int j = 0; j < 8; j++){ \
            int s_ = j >> 2, n_ = rb + (j & 3)*32; \
            int p_ = (((kb) & 1) << 1) + s_; \
            cpa16(sbase + (4*CH + (buf)*2*CH + s_*CH + n_*LDK + c4v)*4, \
                  Wz1 + (size_t)(nt*128 + n_)*(4*HD) + p_*HD + ((kb)>>1)*32 + c4v); \
        } CP_COMMIT(); }
    // facts/q/m prefetch for block kb
    #define G_LDG_A(kb) { \
        int j_ = ((kb)>>1)*32 + c4v; \
        _Pragma("unroll") for (int it = 0; it < 4; it++) \
            pf[it] = *reinterpret_cast<const float4*>(fb + (size_t)(rb + it*32)*HD + j_); \
        pq  = *reinterpret_cast<const float4*>(qb + j_); \
        pmv = *reinterpret_cast<const float4*>(mb + j_); }
    // z build + tf32 STS for block kb into buffer buf
    #define G_STS_A(kb, buf) { \
        _Pragma("unroll") for (int it = 0; it < 8; it++){ \
            int s_ = it >> 2, r_ = rb + (it & 3)*32; \
            int p_ = (((kb) & 1) << 1) + s_; \
            float4 f_ = pf[it & 3]; float4 z_; \
            if (p_ == 0){      z_.x=f_.x*pq.x;  z_.y=f_.y*pq.y;  z_.z=f_.z*pq.z;  z_.w=f_.w*pq.w; } \
            else if (p_ == 1){ z_.x=f_.x*pmv.x; z_.y=f_.y*pmv.y; z_.z=f_.z*pmv.z; z_.w=f_.w*pmv.w; } \
            else if (p_ == 2){ z_.x=fabsf(f_.x-pq.x);  z_.y=fabsf(f_.y-pq.y);  z_.z=fabsf(f_.z-pq.z);  z_.w=fabsf(f_.w-pq.w); } \
            else {             z_.x=fabsf(f_.x-pmv.x); z_.y=fabsf(f_.y-pmv.y); z_.z=fabsf(f_.z-pmv.z); z_.w=fabsf(f_.w-pmv.w); } \
            unsigned* d_ = us + (buf)*2*CH + s_*CH + r_*LDK + c4v; \
            d_[0]=f2tf(z_.x); d_[1]=f2tf(z_.y); d_[2]=f2tf(z_.z); d_[3]=f2tf(z_.w); \
        } }

    // prologue
    G_LDG_A(0); G_STS_A(0, 0); G_ISSUE_B(0, 0); G_LDG_A(1);

    const int NBLK = (4*HD)/64;  // 64
    for (int i = 0; i < NBLK; i++){
        int buf = i & 1;
        CP_WAIT(0);
        __syncthreads();
        if (i + 1 < NBLK){
            G_ISSUE_B(i+1, buf^1);
            G_STS_A(i+1, buf^1);
            if (i + 2 < NBLK) G_LDG_A(i+2);
        }
        const unsigned* Ab = us + buf*2*CH;
        const unsigned* Bb = us + 4*CH + buf*2*CH;
        #pragma unroll
        for (int ks = 0; ks < 8; ks++)
            kstep8<0,1>(Ab + (ks>>2)*CH, Bb + (ks>>2)*CH, (ks&3)*8 + lk, acc, warp_m, warp_n, lg);
    }

    // epilogue: sum_h tanh(acc + bz1[h]) * Wz2[h] -> atomicAdd logits
    float rs[4] = {0.f, 0.f, 0.f, 0.f};
    #pragma unroll
    for (int mi = 0; mi < 2; mi++)
        #pragma unroll
        for (int ni = 0; ni < 8; ni++){
            int c0 = nt*128 + warp_n + ni*8 + lk*2;
            float w0 = Wz2[c0], w1 = Wz2[c0+1];
            float z0 = bz1[c0], z1 = bz1[c0+1];
            rs[mi*2+0] += tanhf(acc[mi][ni][0]+z0)*w0 + tanhf(acc[mi][ni][1]+z1)*w1;
            rs[mi*2+1] += tanhf(acc[mi][ni][2]+z0)*w0 + tanhf(acc[mi][ni][3]+z1)*w1;
        }
    #pragma unroll
    for (int r = 0; r < 4; r++){
        rs[r] += __shfl_xor_sync(0xffffffffu, rs[r], 1);
        rs[r] += __shfl_xor_sync(0xffffffffu, rs[r], 2);
    }
    if (lk == 0){
        int s0 = warp_m + lg;
        atomicAdd(&g_Glogit[bt*NS + s0     ], rs[0]);
        atomicAdd(&g_Glogit[bt*NS + s0 + 8 ], rs[1]);
        atomicAdd(&g_Glogit[bt*NS + s0 + 16], rs[2]);
        atomicAdd(&g_Glogit[bt*NS + s0 + 24], rs[3]);
    }
}

// ================= K3: FR/FW (fully cp.async pipelined) =================
__global__ void __launch_bounds__(256,1) k2_F(
        const float* __restrict__ facts,
        const float* __restrict__ Wr, const float* __restrict__ br,
        const float* __restrict__ W,  const float* __restrict__ bw){
    extern __shared__ unsigned us[];
    uint32_t sbase = smem_u32(us);
    int tid = threadIdx.x, wid = tid >> 5, lane = tid & 31;
    int lg = lane >> 2, lk = lane & 3;
    int warp_m = (wid >> 1) * 32, warp_n = (wid & 1) * 64;
    int nt = blockIdx.x, bt = blockIdx.y, which = blockIdx.z;
    const float* Wsel = which ? W  : Wr;
    const float* bsel = which ? bw : br;
    float* Out = which ? g_FW : g_FR;
    int c4v = (tid & 7) * 4, rb = tid >> 3;
    const float* fb = facts + (size_t)bt*NS*HD;
    float acc[2][8][4]; ZERO_ACC(acc);

    #define F_ISSUE(kb, buf) { \
        _Pragma("unroll") for (int j = 0; j < 8; j++){ \
            int s_ = j >> 2, r_ = rb + (j & 3)*32; \
            cpa16(sbase + ((buf)*2*CH + s_*CH + r_*LDK + c4v)*4, \
                  fb + (size_t)r_*HD + (kb)*64 + s_*32 + c4v); \
            cpa16(sbase + (4*CH + (buf)*2*CH + s_*CH + r_*LDK + c4v)*4, \
                  Wsel + (size_t)(nt*128 + r_)*HD + (kb)*64 + s_*32 + c4v); \
        } CP_COMMIT(); }

    F_ISSUE(0, 0);
    const int NBLK = HD/64;  // 16
    for (int i = 0; i < NBLK; i++){
        int buf = i & 1;
        CP_WAIT(0);
        __syncthreads();
        if (i + 1 < NBLK) F_ISSUE(i+1, buf^1);
        const unsigned* Ab = us + buf*2*CH;
        const unsigned* Bb = us + 4*CH + buf*2*CH;
        #pragma unroll
        for (int ks = 0; ks < 8; ks++)
            kstep8<1,1>(Ab + (ks>>2)*CH, Bb + (ks>>2)*CH, (ks&3)*8 + lk, acc, warp_m, warp_n, lg);
    }

    // epilogue: + bias, store [s][b][h]
    #pragma unroll
    for (int mi = 0; mi < 2; mi++){
        int r0 = warp_m + mi*16 + lg;   // s index
        #pragma unroll
        for (int ni = 0; ni < 8; ni++){
            int h = nt*128 + warp_n + ni*8 + lk*2;
            float b0 = bsel[h], b1 = bsel[h+1];
            float2 v0 = make_float2(acc[mi][ni][0]+b0, acc[mi][ni][1]+b1);
            float2 v1 = make_float2(acc[mi][ni][2]+b0, acc[mi][ni][3]+b1);
            *reinterpret_cast<float2*>(Out + (size_t)r0*(NB*HD) + (size_t)bt*HD + h) = v0;
            *reinterpret_cast<float2*>(Out + (size_t)(r0+8)*(NB*HD) + (size_t)bt*HD + h) = v1;
        }
    }
}

// ---------------- K2: softmax ----------------
__global__ void k_softmax(){
    int bt = blockIdx.x, t = threadIdx.x;
    float v = g_Glogit[bt*NS + t];
    __shared__ float sm_[4], ss[4];
    float mx = v;
    #pragma unroll
    for (int o = 16; o; o >>= 1) mx = fmaxf(mx, __shfl_xor_sync(0xffffffffu, mx, o));
    if ((t & 31) == 0) sm_[t >> 5] = mx;
    __syncthreads();
    mx = fmaxf(fmaxf(sm_[0], sm_[1]), fmaxf(sm_[2], sm_[3]));
    float e = __expf(v - mx);
    float sum = e;
    #pragma unroll
    for (int o = 16; o; o >>= 1) sum += __shfl_xor_sync(0xffffffffu, sum, o);
    if ((t & 31) == 0) ss[t >> 5] = sum;
    __syncthreads();
    sum = ss[0] + ss[1] + ss[2] + ss[3];
    g_Gt[t*NB + bt] = e / sum;
}

// ---------------- K4: persistent scan ----------------
__device__ __forceinline__ void grid_sync(unsigned &target){
    __syncthreads();
    if (threadIdx.x == 0){
        __threadfence();
        atomicAdd(&g_barctr, 1u);
        target += NCTA_SCAN;
        while (atomicAdd(&g_barctr, 0u) < target) { __nanosleep(32); }
    }
    __syncthreads();
}
__device__ __forceinline__ float gru_upd(float fr, float fw, float y1, float y2,
                                         float b_ur, float b_u, float c, float g){
    float r  = 1.f / (1.f + __expf(-(fr + y1 + b_ur)));
    float ht = tanhf(fw + r * (y2 + b_u));
    return g * ht + (1.f - g) * c;
}

__global__ void __launch_bounds__(256,1) k2_scan(
        const float* __restrict__ Ur, const float* __restrict__ bur,
        const float* __restrict__ U,  const float* __restrict__ bu){
    extern __shared__ unsigned us[];   // A: us[0..4CH) raw C-slice; B: us[4CH..8CH) tf32 weights
    uint32_t sbase = smem_u32(us);
    int cta = blockIdx.x, tid = threadIdx.x;
    int wid = tid >> 5, lane = tid & 31, lg = lane >> 2, lk = lane & 3;
    int warp_m = (wid >> 1) * 32, warp_n = (wid & 1) * 64;
    int c4v = (tid & 7) * 4, rb = tid >> 3;
    int nt = cta >> 3;              // 0..15: 0-7 -> Y1 (Ur), 8-15 -> Y2 (U)
    int kcb = (cta & 7) * 128;      // K slice
    const float* Wsel = (nt < 8) ? Ur : U;
    int nbase = (nt & 7) * 128;
    float* P = g_part + (size_t)cta * 16384;

    // preload + convert weight tile once (resident all 128 steps)
    #pragma unroll
    for (int j = 0; j < 16; j++){
        int s = j >> 2, n = rb + (j & 3)*32;
        float4 v = *reinterpret_cast<const float4*>(Wsel + (size_t)(nbase+n)*HD + kcb + s*32 + c4v);
        unsigned* d = us + 4*CH + s*CH + n*LDK + c4v;
        d[0]=f2tf(v.x); d[1]=f2tf(v.y); d[2]=f2tf(v.z); d[3]=f2tf(v.w);
    }
    __syncthreads();

    // phase-B element ownership (4 consecutive elements of C per thread)
    int e  = (cta*256 + tid) * 4;
    int eb = e >> 10, eh = e & (HD-1);
    int nt1 = eh >> 7, hm = eh & 127;

    unsigned target = 0;
    for (int s = 0; s < NS; s++){
        // ---- phase A: issue C-slice (4 groups), pipelined compute
        #pragma unroll
        for (int sg = 0; sg < 4; sg++){
            #pragma unroll
            for (int j = 0; j < 4; j++){
                int r = rb + j*32;
                cpa16(sbase + (sg*CH + r*LDK + c4v)*4,
                      g_C + (size_t)r*HD + kcb + sg*32 + c4v);
            }
            CP_COMMIT();
        }
        float acc[2][8][4]; ZERO_ACC(acc);
        #pragma unroll
        for (int sub = 0; sub < 4; sub++){
            if (sub == 0)      CP_WAIT(3);
            else if (sub == 1) CP_WAIT(2);
            else if (sub == 2) CP_WAIT(1);
            else               CP_WAIT(0);
            __syncthreads();
            const unsigned* Ab = us + sub*CH;
            const unsigned* Bb = us + 4*CH + sub*CH;
            #pragma unroll
            for (int kk = 0; kk < 4; kk++)
                kstep8<1,0>(Ab, Bb, kk*8 + lk, acc, warp_m, warp_n, lg);
        }
        #pragma unroll
        for (int mi = 0; mi < 2; mi++){
            int r0 = warp_m + mi*16 + lg;
            #pragma unroll
            for (int ni = 0; ni < 8; ni++){
                int c = warp_n + ni*8 + lk*2;
                __stcg(reinterpret_cast<float2*>(P + r0*128 + c),
                       make_float2(acc[mi][ni][0], acc[mi][ni][1]));
                __stcg(reinterpret_cast<float2*>(P + (r0+8)*128 + c),
                       make_float2(acc[mi][ni][2], acc[mi][ni][3]));
            }
        }
        grid_sync(target);

        // ---- phase B: reduce partials, GRU update of C
        float4 y1 = make_float4(0,0,0,0), y2 = make_float4(0,0,0,0);
        #pragma unroll
        for (int kk = 0; kk < 8; kk++){
            float4 p1 = __ldcg(reinterpret_cast<const float4*>(
                g_part + (size_t)(nt1*8 + kk)*16384 + eb*128 + hm));
            float4 p2 = __ldcg(reinterpret_cast<const float4*>(
                g_part + (size_t)((nt1+8)*8 + kk)*16384 + eb*128 + hm));
            y1.x += p1.x; y1.y += p1.y; y1.z += p1.z; y1.w += p1.w;
            y2.x += p2.x; y2.y += p2.y; y2.z += p2.z; y2.w += p2.w;
        }
        float4 fr = *reinterpret_cast<const float4*>(g_FR + (size_t)s*NB*HD + (size_t)eb*HD + eh);
        float4 fw = *reinterpret_cast<const float4*>(g_FW + (size_t)s*NB*HD + (size_t)eb*HD + eh);
        float4 co = __ldcg(reinterpret_cast<const float4*>(g_C + (size_t)eb*HD + eh));
        float4 vur = *reinterpret_cast<const float4*>(bur + eh);
        float4 vu  = *reinterpret_cast<const float4*>(bu + eh);
        float gg = g_Gt[s*NB + eb];
        float4 cn;
        cn.x = gru_upd(fr.x, fw.x, y1.x, y2.x, vur.x, vu.x, co.x, gg);
        cn.y = gru_upd(fr.y, fw.y, y1.y, y2.y, vur.y, vu.y, co.y, gg);
        cn.z = gru_upd(fr.z, fw.z, y1.z, y2.z, vur.z, vu.z, co.z, gg);
        cn.w = gru_upd(fr.w, fw.w, y1.w, y2.w, vur.w, vu.w, co.w, gg);
        __stcg(reinterpret_cast<float4*>(g_C + (size_t)eb*HD + eh), cn);
        grid_sync(target);
    }
}

// ---------------- K5: final GEMM (legacy path, small) ----------------
__device__ __forceinline__ void compute_chunk(const unsigned* As, const unsigned* Bs,
        float acc[2][8][4], int warp_m, int warp_n, int lg, int lk){
    #pragma unroll
    for (int ks = 0; ks < 4; ks++){
        int k0 = ks*8 + lk;
        unsigned a[2][4], b[8][2];
        #pragma unroll
        for (int mi = 0; mi < 2; mi++){
            int m0 = warp_m + mi*16 + lg;
            a[mi][0] = As[m0*LDK + k0];
            a[mi][1] = As[(m0+8)*LDK + k0];
            a[mi][2] = As[m0*LDK + k0+4];
            a[mi][3] = As[(m0+8)*LDK + k0+4];
        }
        #pragma unroll
        for (int ni = 0; ni < 8; ni++){
            int n0 = warp_n + ni*8 + lg;
            b[ni][0] = Bs[n0*LDK + k0];
            b[ni][1] = Bs[n0*LDK + k0+4];
        }
        #pragma unroll
        for (int mi = 0; mi < 2; mi++)
            #pragma unroll
            for (int ni = 0; ni < 8; ni++)
                mma8(acc[mi][ni], a[mi], b[ni]);
    }
}
__global__ void k_out(const float* __restrict__ pm, const float* __restrict__ q,
                      const float* __restrict__ Wm){
    __shared__ unsigned As[128*LDK];
    __shared__ unsigned Bs[128*LDK];
    int nt = blockIdx.x;
    int ks = blockIdx.y;
    int kbase = ks * 256;
    int tid = threadIdx.x, wid = tid >> 5, lane = tid & 31, lg = lane >> 2, lk = lane & 3;
    int warp_m = (wid >> 1) * 32, warp_n = (wid & 1) * 64;
    float acc[2][8][4]; ZERO_ACC(acc);

    for (int kc = 0; kc < 256; kc += 32){
        int kg = kbase + kc;
        int seg = kg >> 10;
        int jj = kg & (HD-1);
        #pragma unroll
        for (int i = 0; i < 4; i++){
            int slot = tid + i*256;
            int bb = slot >> 3, c4 = (slot & 7) * 4;
            float4 v;
            if (seg == 0)      v = *reinterpret_cast<const float4*>(pm + (size_t)bb*HD + jj + c4);
            else if (seg == 1) v = __ldcg(reinterpret_cast<const float4*>(g_C + (size_t)bb*HD + jj + c4));
            else               v = *reinterpret_cast<const float4*>(q + (size_t)bb*HD + jj + c4);
            As[bb*LDK + c4+0] = f2tf(v.x);
            As[bb*LDK + c4+1] = f2tf(v.y);
            As[bb*LDK + c4+2] = f2tf(v.z);
            As[bb*LDK + c4+3] = f2tf(v.w);
        }
        #pragma unroll
        for (int i = 0; i < 4; i++){
            int slot = tid + i*256;
            int n = slot >> 3, c4 = (slot & 7) * 4;
            float4 v = *reinterpret_cast<const float4*>(Wm + (size_t)(nt*128+n)*(3*HD) + kg + c4);
            Bs[n*LDK + c4+0] = f2tf(v.x);
            Bs[n*LDK + c4+1] = f2tf(v.y);
            Bs[n*LDK + c4+2] = f2tf(v.z);
            Bs[n*LDK + c4+3] = f2tf(v.w);
        }
        __syncthreads();
        compute_chunk(As, Bs, acc, warp_m, warp_n, lg, lk);
        __syncthreads();
    }
    #pragma unroll
    for (int mi = 0; mi < 2; mi++){
        int r0 = warp_m + mi*16 + lg;
        #pragma unroll
        for (int ni = 0; ni < 8; ni++){
            int h = nt*128 + warp_n + ni*8 + lk*2;
            atomicAdd(&g_Otmp[(size_t)r0*HD + h     ], acc[mi][ni][0]);
            atomicAdd(&g_Otmp[(size_t)r0*HD + h + 1 ], acc[mi][ni][1]);
            atomicAdd(&g_Otmp[(size_t)(r0+8)*HD + h    ], acc[mi][ni][2]);
            atomicAdd(&g_Otmp[(size_t)(r0+8)*HD + h + 1], acc[mi][ni][3]);
        }
    }
}

// ---------------- K6: bias + relu -> output ----------------
__global__ void k_finish(const float* __restrict__ bm, float* __restrict__ out){
    int i = blockIdx.x * blockDim.x + threadIdx.x;
    if (i < NB*HD){
        float v = g_Otmp[i] + bm[i & (HD-1)];
        out[i] = fmaxf(v, 0.f);
    }
}

// ---------------- launch ----------------
extern "C" void kernel_launch(void* const* d_in, const int* in_sizes, int n_in,
                              void* d_out, int out_size){
    (void)in_sizes; (void)n_in; (void)out_size;
    const float* facts     = (const float*)d_in[0];
    const float* questions = (const float*)d_in[1];
    const float* prevM     = (const float*)d_in[2];
    const float* Wr  = (const float*)d_in[3];
    const float* br  = (const float*)d_in[4];
    const float* Ur  = (const float*)d_in[5];
    const float* bur = (const float*)d_in[6];
    const float* W   = (const float*)d_in[7];
    const float* bw  = (const float*)d_in[8];
    const float* U   = (const float*)d_in[9];
    const float* bu  = (const float*)d_in[10];
    const float* Wz1 = (const float*)d_in[11];
    const float* bz1 = (const float*)d_in[12];
    const float* Wz2 = (const float*)d_in[13];
    // d_in[14] = bz2: softmax is shift-invariant, cancels exactly.
    const float* Wm  = (const float*)d_in[15];
    const float* bm  = (const float*)d_in[16];
    float* out = (float*)d_out;

    static int attr_done = 0;
    if (!attr_done){
        cudaFuncSetAttribute(k2_G,    cudaFuncAttributeMaxDynamicSharedMemorySize, DYN_SMEM);
        cudaFuncSetAttribute(k2_F,    cudaFuncAttributeMaxDynamicSharedMemorySize, DYN_SMEM);
        cudaFuncSetAttribute(k2_scan, cudaFuncAttributeMaxDynamicSharedMemorySize, DYN_SMEM);
        attr_done = 1;
    }

    k_init<<<512, 256>>>();
    dim3 gG(8, 128);
    k2_G<<<gG, 256, DYN_SMEM>>>(facts, questions, prevM, Wz1, bz1, Wz2);
    k_softmax<<<128, 128>>>();
    dim3 gF(8, 128, 2);
    k2_F<<<gF, 256, DYN_SMEM>>>(facts, Wr, br, W, bw);
    k2_scan<<<NCTA_SCAN, 256, DYN_SMEM>>>(Ur, bur, U, bu);
    dim3 gO(8, 12);
    k_out<<<gO, 256>>>(prevM, questions, Wm);
    k_finish<<<512, 256>>>(bm, out);
}

// round 4
// speedup vs baseline: 1.1304x; 1.0253x over previous
#include <cuda_runtime.h>
#include <cstdint>
#include <cstddef>

#define HD 1024
#define NB 128
#define NS 128
#define NROW (NB*NS)
#define LDK 36
#define CH (128*36)          // uints per 128x32 tile
#define NCTA_SCAN 128
#define GEMM_SMEM (4*CH*4)   // 73728 B  (A x2, B x2)
#define SCAN_SMEM (8*CH*4)   // 147456 B (A x4 subs, B x4 resident)

// ---------------- scratch ----------------
__device__ __align__(16) float g_FR[(size_t)NS*NB*HD];
__device__ __align__(16) float g_FW[(size_t)NS*NB*HD];
__device__ __align__(16) float    g_C[NB*HD];      // raw fp32 state
__device__ __align__(16) unsigned g_Ctf[NB*HD];    // tf32-converted copy of C
__device__ __align__(16) float g_Otmp[NB*HD];
__device__ __align__(16) float g_part[(size_t)NCTA_SCAN*128*128];
__device__ __align__(16) float g_Glogit[NROW];
__device__ __align__(16) float g_Gt[NS*NB];
__device__ unsigned g_barctr;

// ---------------- helpers ----------------
__device__ __forceinline__ unsigned f2tf(float f){
    unsigned u; asm("cvt.rna.tf32.f32 %0, %1;" : "=r"(u) : "f"(f)); return u;
}
__device__ __forceinline__ uint32_t smem_u32(const void* p){
    uint32_t a; asm("{ .reg .u64 t; cvta.to.shared.u64 t, %1; cvt.u32.u64 %0, t; }"
                    : "=r"(a) : "l"(p)); return a;
}
__device__ __forceinline__ void cpa16(uint32_t dst, const void* src){
    asm volatile("cp.async.cg.shared.global [%0], [%1], 16;" :: "r"(dst), "l"(src));
}
#define CP_COMMIT() asm volatile("cp.async.commit_group;" ::: "memory")
#define CP_WAIT(n)  asm volatile("cp.async.wait_group %0;" :: "n"(n) : "memory")

__device__ __forceinline__ void ldsm4(unsigned* r, uint32_t addr){
    asm volatile("ldmatrix.sync.aligned.m8n8.x4.shared.b16 {%0,%1,%2,%3}, [%4];"
        : "=r"(r[0]),"=r"(r[1]),"=r"(r[2]),"=r"(r[3]) : "r"(addr));
}
__device__ __forceinline__ void mma8(float* d, const unsigned* a, const unsigned* b){
    asm volatile("mma.sync.aligned.m16n8k8.row.col.f32.tf32.tf32.f32 "
        "{%0,%1,%2,%3},{%4,%5,%6,%7},{%8,%9},{%0,%1,%2,%3};\n"
        : "+f"(d[0]),"+f"(d[1]),"+f"(d[2]),"+f"(d[3])
        : "r"(a[0]),"r"(a[1]),"r"(a[2]),"r"(a[3]),"r"(b[0]),"r"(b[1]));
}

// One 128x128x32 tile-step via ldmatrix. aBase/bBase: byte smem addr of tile.
// offA0/offA1/offB: per-thread ldmatrix byte offsets.
template<int CVTA, int CVTB>
__device__ __forceinline__ void compute32(uint32_t aBase, uint32_t bBase,
        uint32_t offA0, uint32_t offA1, const uint32_t* offB, float acc[2][8][4]){
    #pragma unroll
    for (int ks = 0; ks < 4; ks++){
        unsigned a0[4], a1[4], bb[4][4];
        ldsm4(a0, aBase + offA0 + ks*32);
        ldsm4(a1, aBase + offA1 + ks*32);
        #pragma unroll
        for (int p = 0; p < 4; p++) ldsm4(bb[p], bBase + offB[p] + ks*32);
        if (CVTA){
            #pragma unroll
            for (int j = 0; j < 4; j++){
                a0[j] = f2tf(__uint_as_float(a0[j]));
                a1[j] = f2tf(__uint_as_float(a1[j]));
            }
        }
        if (CVTB){
            #pragma unroll
            for (int p = 0; p < 4; p++)
                #pragma unroll
                for (int j = 0; j < 4; j++) bb[p][j] = f2tf(__uint_as_float(bb[p][j]));
        }
        #pragma unroll
        for (int mi = 0; mi < 2; mi++){
            const unsigned* a = mi ? a1 : a0;
            #pragma unroll
            for (int p = 0; p < 4; p++){
                unsigned b0[2] = {bb[p][0], bb[p][2]};
                unsigned b1[2] = {bb[p][1], bb[p][3]};
                mma8(acc[mi][2*p],   a, b0);
                mma8(acc[mi][2*p+1], a, b1);
            }
        }
    }
}

// per-thread ldmatrix offsets (bytes)
#define LDSM_OFFSETS() \
    int rowA0 = warp_m + (lane & 7) + ((lane >> 3) & 1)*8; \
    int colw  = ((lane >> 4) & 1)*4; \
    uint32_t offA0 = (uint32_t)(rowA0*LDK + colw)*4; \
    uint32_t offA1 = (uint32_t)((rowA0+16)*LDK + colw)*4; \
    uint32_t offB[4]; \
    _Pragma("unroll") for (int p_ = 0; p_ < 4; p_++) \
        offB[p_] = (uint32_t)((warp_n + p_*16 + (lane & 15))*LDK + colw)*4;

#define ZERO_ACC(acc) { \
    _Pragma("unroll") for (int _i=0;_i<2;_i++) \
    _Pragma("unroll") for (int _j=0;_j<8;_j++) \
    _Pragma("unroll") for (int _k=0;_k<4;_k++) acc[_i][_j][_k]=0.f; }

// ---------------- K0: per-replay init ----------------
__global__ void k_init(){
    int i = blockIdx.x * blockDim.x + threadIdx.x;
    if (i == 0) g_barctr = 0u;
    if (i < NROW) g_Glogit[i] = 0.f;
    if (i < NB*HD){ g_C[i] = 0.f; g_Ctf[i] = 0u; g_Otmp[i] = 0.f; }
}

// ================= K1: G logits =================
// CTA 128(s) x 128(h), K=4096 in 128 blocks of 32. Block i: part=(i&3), fcol=(i>>2)*32.
__global__ void __launch_bounds__(256,2) k3_G(
        const float* __restrict__ facts, const float* __restrict__ q,
        const float* __restrict__ pm, const float* __restrict__ Wz1,
        const float* __restrict__ bz1, const float* __restrict__ Wz2){
    extern __shared__ unsigned us[];
    uint32_t sbase = smem_u32(us);
    int tid = threadIdx.x, wid = tid >> 5, lane = tid & 31;
    int lg = lane >> 2, lk = lane & 3;
    int warp_m = (wid >> 1) * 32, warp_n = (wid & 1) * 64;
    int nt = blockIdx.x, bt = blockIdx.y;
    int c4v = (tid & 7) * 4, rb = tid >> 3;
    LDSM_OFFSETS();
    const float* fb = facts + (size_t)bt*NS*HD;
    const float* qb = q  + (size_t)bt*HD;
    const float* mb = pm + (size_t)bt*HD;

    float4 pf[4];
    float acc[2][8][4]; ZERO_ACC(acc);

    #define G_LDG(i_) { int fc_ = ((i_)>>2)*32 + c4v; \
        _Pragma("unroll") for (int it = 0; it < 4; it++) \
            pf[it] = *reinterpret_cast<const float4*>(fb + (size_t)(rb + it*32)*HD + fc_); }
    #define G_STS(i_, buf_) { int part_ = (i_) & 3; int fc_ = ((i_)>>2)*32 + c4v; \
        float4 qv_ = *reinterpret_cast<const float4*>(qb + fc_); \
        float4 mv_ = *reinterpret_cast<const float4*>(mb + fc_); \
        _Pragma("unroll") for (int it = 0; it < 4; it++){ \
            float4 f_ = pf[it]; float4 z_; \
            if (part_ == 0){      z_.x=f_.x*qv_.x; z_.y=f_.y*qv_.y; z_.z=f_.z*qv_.z; z_.w=f_.w*qv_.w; } \
            else if (part_ == 1){ z_.x=f_.x*mv_.x; z_.y=f_.y*mv_.y; z_.z=f_.z*mv_.z; z_.w=f_.w*mv_.w; } \
            else if (part_ == 2){ z_.x=fabsf(f_.x-qv_.x); z_.y=fabsf(f_.y-qv_.y); z_.z=fabsf(f_.z-qv_.z); z_.w=fabsf(f_.w-qv_.w); } \
            else {               z_.x=fabsf(f_.x-mv_.x); z_.y=fabsf(f_.y-mv_.y); z_.z=fabsf(f_.z-mv_.z); z_.w=fabsf(f_.w-mv_.w); } \
            unsigned* d_ = us + (buf_)*CH + (rb + it*32)*LDK + c4v; \
            d_[0]=f2tf(z_.x); d_[1]=f2tf(z_.y); d_[2]=f2tf(z_.z); d_[3]=f2tf(z_.w); } }
    #define G_CPB(i_, buf_) { int part_ = (i_) & 3; int fc_ = ((i_)>>2)*32; \
        _Pragma("unroll") for (int j = 0; j < 4; j++){ int n_ = rb + j*32; \
            cpa16(sbase + ((2 + (buf_))*CH + n_*LDK + c4v)*4, \
                  Wz1 + (size_t)(nt*128 + n_)*(4*HD) + part_*HD + fc_ + c4v); } CP_COMMIT(); }

    G_LDG(0); G_CPB(0, 0);
    const int NBLK = 128;
    for (int i = 0; i < NBLK; i++){
        int buf = i & 1;
        G_STS(i, buf);
        if (((i+1) & 3) == 0 && i+1 < NBLK) G_LDG(i+1);
        CP_WAIT(0);
        __syncthreads();
        if (i+1 < NBLK) G_CPB(i+1, buf^1);
        compute32<0,1>(sbase + buf*CH*4, sbase + (2+buf)*CH*4, offA0, offA1, offB, acc);
    }

    float rs[4] = {0.f, 0.f, 0.f, 0.f};
    #pragma unroll
    for (int mi = 0; mi < 2; mi++)
        #pragma unroll
        for (int ni = 0; ni < 8; ni++){
            int c0 = nt*128 + warp_n + ni*8 + lk*2;
            float w0 = Wz2[c0], w1 = Wz2[c0+1];
            float z0 = bz1[c0], z1 = bz1[c0+1];
            rs[mi*2+0] += tanhf(acc[mi][ni][0]+z0)*w0 + tanhf(acc[mi][ni][1]+z1)*w1;
            rs[mi*2+1] += tanhf(acc[mi][ni][2]+z0)*w0 + tanhf(acc[mi][ni][3]+z1)*w1;
        }
    #pragma unroll
    for (int r = 0; r < 4; r++){
        rs[r] += __shfl_xor_sync(0xffffffffu, rs[r], 1);
        rs[r] += __shfl_xor_sync(0xffffffffu, rs[r], 2);
    }
    if (lk == 0){
        int s0 = warp_m + lg;
        atomicAdd(&g_Glogit[bt*NS + s0     ], rs[0]);
        atomicAdd(&g_Glogit[bt*NS + s0 + 8 ], rs[1]);
        atomicAdd(&g_Glogit[bt*NS + s0 + 16], rs[2]);
        atomicAdd(&g_Glogit[bt*NS + s0 + 24], rs[3]);
    }
}

// ================= K3: FR/FW =================
__global__ void __launch_bounds__(256,2) k3_F(
        const float* __restrict__ facts,
        const float* __restrict__ Wr, const float* __restrict__ br,
        const float* __restrict__ W,  const float* __restrict__ bw){
    extern __shared__ unsigned us[];
    uint32_t sbase = smem_u32(us);
    int tid = threadIdx.x, wid = tid >> 5, lane = tid & 31;
    int lg = lane >> 2, lk = lane & 3;
    int warp_m = (wid >> 1) * 32, warp_n = (wid & 1) * 64;
    int nt = blockIdx.x, bt = blockIdx.y, which = blockIdx.z;
    const float* Wsel = which ? W  : Wr;
    const float* bsel = which ? bw : br;
    float* Out = which ? g_FW : g_FR;
    int c4v = (tid & 7) * 4, rb = tid >> 3;
    LDSM_OFFSETS();
    const float* fb = facts + (size_t)bt*NS*HD;
    float4 pf[4];
    float acc[2][8][4]; ZERO_ACC(acc);

    #define F_LDG(i_) { \
        _Pragma("unroll") for (int it = 0; it < 4; it++) \
            pf[it] = *reinterpret_cast<const float4*>(fb + (size_t)(rb + it*32)*HD + (i_)*32 + c4v); }
    #define F_STS(buf_) { \
        _Pragma("unroll") for (int it = 0; it < 4; it++){ \
            unsigned* d_ = us + (buf_)*CH + (rb + it*32)*LDK + c4v; \
            d_[0]=f2tf(pf[it].x); d_[1]=f2tf(pf[it].y); d_[2]=f2tf(pf[it].z); d_[3]=f2tf(pf[it].w); } }
    #define F_CPB(i_, buf_) { \
        _Pragma("unroll") for (int j = 0; j < 4; j++){ int n_ = rb + j*32; \
            cpa16(sbase + ((2 + (buf_))*CH + n_*LDK + c4v)*4, \
                  Wsel + (size_t)(nt*128 + n_)*HD + (i_)*32 + c4v); } CP_COMMIT(); }

    F_LDG(0); F_CPB(0, 0);
    const int NBLK = 32;
    for (int i = 0; i < NBLK; i++){
        int buf = i & 1;
        F_STS(buf);
        if (i+1 < NBLK) F_LDG(i+1);
        CP_WAIT(0);
        __syncthreads();
        if (i+1 < NBLK) F_CPB(i+1, buf^1);
        compute32<0,1>(sbase + buf*CH*4, sbase + (2+buf)*CH*4, offA0, offA1, offB, acc);
    }

    #pragma unroll
    for (int mi = 0; mi < 2; mi++){
        int r0 = warp_m + mi*16 + lg;   // s index
        #pragma unroll
        for (int ni = 0; ni < 8; ni++){
            int h = nt*128 + warp_n + ni*8 + lk*2;
            float b0 = bsel[h], b1 = bsel[h+1];
            float2 v0 = make_float2(acc[mi][ni][0]+b0, acc[mi][ni][1]+b1);
            float2 v1 = make_float2(acc[mi][ni][2]+b0, acc[mi][ni][3]+b1);
            *reinterpret_cast<float2*>(Out + (size_t)r0*(NB*HD) + (size_t)bt*HD + h) = v0;
            *reinterpret_cast<float2*>(Out + (size_t)(r0+8)*(NB*HD) + (size_t)bt*HD + h) = v1;
        }
    }
}

// ---------------- K2: softmax ----------------
__global__ void k_softmax(){
    int bt = blockIdx.x, t = threadIdx.x;
    float v = g_Glogit[bt*NS + t];
    __shared__ float sm_[4], ss[4];
    float mx = v;
    #pragma unroll
    for (int o = 16; o; o >>= 1) mx = fmaxf(mx, __shfl_xor_sync(0xffffffffu, mx, o));
    if ((t & 31) == 0) sm_[t >> 5] = mx;
    __syncthreads();
    mx = fmaxf(fmaxf(sm_[0], sm_[1]), fmaxf(sm_[2], sm_[3]));
    float e = __expf(v - mx);
    float sum = e;
    #pragma unroll
    for (int o = 16; o; o >>= 1) sum += __shfl_xor_sync(0xffffffffu, sum, o);
    if ((t & 31) == 0) ss[t >> 5] = sum;
    __syncthreads();
    sum = ss[0] + ss[1] + ss[2] + ss[3];
    g_Gt[t*NB + bt] = e / sum;
}

// ---------------- K4: persistent scan ----------------
__device__ __forceinline__ void grid_sync(unsigned &target){
    __syncthreads();
    if (threadIdx.x == 0){
        __threadfence();
        atomicAdd(&g_barctr, 1u);
        target += NCTA_SCAN;
        while (atomicAdd(&g_barctr, 0u) < target) { __nanosleep(32); }
    }
    __syncthreads();
}
__device__ __forceinline__ float gru_upd(float fr, float fw, float y1, float y2,
                                         float b_ur, float b_u, float c, float g){
    float r  = 1.f / (1.f + __expf(-(fr + y1 + b_ur)));
    float ht = tanhf(fw + r * (y2 + b_u));
    return g * ht + (1.f - g) * c;
}

__global__ void __launch_bounds__(256,1) k3_scan(
        const float* __restrict__ Ur, const float* __restrict__ bur,
        const float* __restrict__ U,  const float* __restrict__ bu){
    extern __shared__ unsigned us[];   // A subs: [0,4CH); B resident tf32: [4CH,8CH)
    uint32_t sbase = smem_u32(us);
    int cta = blockIdx.x, tid = threadIdx.x;
    int wid = tid >> 5, lane = tid & 31, lg = lane >> 2, lk = lane & 3;
    int warp_m = (wid >> 1) * 32, warp_n = (wid & 1) * 64;
    int c4v = (tid & 7) * 4, rb = tid >> 3;
    LDSM_OFFSETS();
    int nt = cta >> 3;              // 0..15: 0-7 -> Y1 (Ur), 8-15 -> Y2 (U)
    int kcb = (cta & 7) * 128;      // K slice
    const float* Wsel = (nt < 8) ? Ur : U;
    int nbase = (nt & 7) * 128;
    float* P = g_part + (size_t)cta * 16384;

    // weights resident, tf32, all 128 steps
    #pragma unroll
    for (int j = 0; j < 16; j++){
        int s = j >> 2, n = rb + (j & 3)*32;
        float4 v = *reinterpret_cast<const float4*>(Wsel + (size_t)(nbase+n)*HD + kcb + s*32 + c4v);
        unsigned* d = us + 4*CH + s*CH + n*LDK + c4v;
        d[0]=f2tf(v.x); d[1]=f2tf(v.y); d[2]=f2tf(v.z); d[3]=f2tf(v.w);
    }
    __syncthreads();

    int e  = (cta*256 + tid) * 4;
    int eb = e >> 10, eh = e & (HD-1);
    int nt1 = eh >> 7, hm = eh & 127;

    unsigned target = 0;
    for (int s = 0; s < NS; s++){
        // ---- phase A: cp.async pre-converted C slice (4 groups), ldmatrix compute
        #pragma unroll
        for (int sg = 0; sg < 4; sg++){
            #pragma unroll
            for (int j = 0; j < 4; j++){
                int r = rb + j*32;
                cpa16(sbase + (sg*CH + r*LDK + c4v)*4,
                      g_Ctf + (size_t)r*HD + kcb + sg*32 + c4v);
            }
            CP_COMMIT();
        }
        float acc[2][8][4]; ZERO_ACC(acc);
        #pragma unroll
        for (int sub = 0; sub < 4; sub++){
            if (sub == 0)      CP_WAIT(3);
            else if (sub == 1) CP_WAIT(2);
            else if (sub == 2) CP_WAIT(1);
            else               CP_WAIT(0);
            __syncthreads();
            compute32<0,0>(sbase + sub*CH*4, sbase + (4+sub)*CH*4, offA0, offA1, offB, acc);
        }
        #pragma unroll
        for (int mi = 0; mi < 2; mi++){
            int r0 = warp_m + mi*16 + lg;
            #pragma unroll
            for (int ni = 0; ni < 8; ni++){
                int c = warp_n + ni*8 + lk*2;
                __stcg(reinterpret_cast<float2*>(P + r0*128 + c),
                       make_float2(acc[mi][ni][0], acc[mi][ni][1]));
                __stcg(reinterpret_cast<float2*>(P + (r0+8)*128 + c),
                       make_float2(acc[mi][ni][2], acc[mi][ni][3]));
            }
        }
        grid_sync(target);

        // ---- phase B: reduce partials, GRU update, write C (raw + tf32)
        float4 y1 = make_float4(0,0,0,0), y2 = make_float4(0,0,0,0);
        #pragma unroll
        for (int kk = 0; kk < 8; kk++){
            float4 p1 = __ldcg(reinterpret_cast<const float4*>(
                g_part + (size_t)(nt1*8 + kk)*16384 + eb*128 + hm));
            float4 p2 = __ldcg(reinterpret_cast<const float4*>(
                g_part + (size_t)((nt1+8)*8 + kk)*16384 + eb*128 + hm));
            y1.x += p1.x; y1.y += p1.y; y1.z += p1.z; y1.w += p1.w;
            y2.x += p2.x; y2.y += p2.y; y2.z += p2.z; y2.w += p2.w;
        }
        float4 fr = *reinterpret_cast<const float4*>(g_FR + (size_t)s*NB*HD + (size_t)eb*HD + eh);
        float4 fw = *reinterpret_cast<const float4*>(g_FW + (size_t)s*NB*HD + (size_t)eb*HD + eh);
        float4 co = __ldcg(reinterpret_cast<const float4*>(g_C + (size_t)eb*HD + eh));
        float4 vur = *reinterpret_cast<const float4*>(bur + eh);
        float4 vu  = *reinterpret_cast<const float4*>(bu + eh);
        float gg = g_Gt[s*NB + eb];
        float4 cn;
        cn.x = gru_upd(fr.x, fw.x, y1.x, y2.x, vur.x, vu.x, co.x, gg);
        cn.y = gru_upd(fr.y, fw.y, y1.y, y2.y, vur.y, vu.y, co.y, gg);
        cn.z = gru_upd(fr.z, fw.z, y1.z, y2.z, vur.z, vu.z, co.z, gg);
        cn.w = gru_upd(fr.w, fw.w, y1.w, y2.w, vur.w, vu.w, co.w, gg);
        __stcg(reinterpret_cast<float4*>(g_C + (size_t)eb*HD + eh), cn);
        uint4 ct;
        ct.x = f2tf(cn.x); ct.y = f2tf(cn.y); ct.z = f2tf(cn.z); ct.w = f2tf(cn.w);
        __stcg(reinterpret_cast<uint4*>(g_Ctf + (size_t)eb*HD + eh), ct);
        grid_sync(target);
    }
}

// ---------------- K5: final GEMM (legacy, small) ----------------
__device__ __forceinline__ void compute_chunk(const unsigned* As, const unsigned* Bs,
        float acc[2][8][4], int warp_m, int warp_n, int lg, int lk){
    #pragma unroll
    for (int ks = 0; ks < 4; ks++){
        int k0 = ks*8 + lk;
        unsigned a[2][4], b[8][2];
        #pragma unroll
        for (int mi = 0; mi < 2; mi++){
            int m0 = warp_m + mi*16 + lg;
            a[mi][0] = As[m0*LDK + k0];
            a[mi][1] = As[(m0+8)*LDK + k0];
            a[mi][2] = As[m0*LDK + k0+4];
            a[mi][3] = As[(m0+8)*LDK + k0+4];
        }
        #pragma unroll
        for (int ni = 0; ni < 8; ni++){
            int n0 = warp_n + ni*8 + lg;
            b[ni][0] = Bs[n0*LDK + k0];
            b[ni][1] = Bs[n0*LDK + k0+4];
        }
        #pragma unroll
        for (int mi = 0; mi < 2; mi++)
            #pragma unroll
            for (int ni = 0; ni < 8; ni++)
                mma8(acc[mi][ni], a[mi], b[ni]);
    }
}
__global__ void k_out(const float* __restrict__ pm, const float* __restrict__ q,
                      const float* __restrict__ Wm){
    __shared__ unsigned As[128*LDK];
    __shared__ unsigned Bs[128*LDK];
    int nt = blockIdx.x;
    int ks = blockIdx.y;
    int kbase = ks * 256;
    int tid = threadIdx.x, wid = tid >> 5, lane = tid & 31, lg = lane >> 2, lk = lane & 3;
    int warp_m = (wid >> 1) * 32, warp_n = (wid & 1) * 64;
    float acc[2][8][4]; ZERO_ACC(acc);

    for (int kc = 0; kc < 256; kc += 32){
        int kg = kbase + kc;
        int seg = kg >> 10;
        int jj = kg & (HD-1);
        #pragma unroll
        for (int i = 0; i < 4; i++){
            int slot = tid + i*256;
            int bb = slot >> 3, c4 = (slot & 7) * 4;
            float4 v;
            if (seg == 0)      v = *reinterpret_cast<const float4*>(pm + (size_t)bb*HD + jj + c4);
            else if (seg == 1) v = __ldcg(reinterpret_cast<const float4*>(g_C + (size_t)bb*HD + jj + c4));
            else               v = *reinterpret_cast<const float4*>(q + (size_t)bb*HD + jj + c4);
            As[bb*LDK + c4+0] = f2tf(v.x);
            As[bb*LDK + c4+1] = f2tf(v.y);
            As[bb*LDK + c4+2] = f2tf(v.z);
            As[bb*LDK + c4+3] = f2tf(v.w);
        }
        #pragma unroll
        for (int i = 0; i < 4; i++){
            int slot = tid + i*256;
            int n = slot >> 3, c4 = (slot & 7) * 4;
            float4 v = *reinterpret_cast<const float4*>(Wm + (size_t)(nt*128+n)*(3*HD) + kg + c4);
            Bs[n*LDK + c4+0] = f2tf(v.x);
            Bs[n*LDK + c4+1] = f2tf(v.y);
            Bs[n*LDK + c4+2] = f2tf(v.z);
            Bs[n*LDK + c4+3] = f2tf(v.w);
        }
        __syncthreads();
        compute_chunk(As, Bs, acc, warp_m, warp_n, lg, lk);
        __syncthreads();
    }
    #pragma unroll
    for (int mi = 0; mi < 2; mi++){
        int r0 = warp_m + mi*16 + lg;
        #pragma unroll
        for (int ni = 0; ni < 8; ni++){
            int h = nt*128 + warp_n + ni*8 + lk*2;
            atomicAdd(&g_Otmp[(size_t)r0*HD + h     ], acc[mi][ni][0]);
            atomicAdd(&g_Otmp[(size_t)r0*HD + h + 1 ], acc[mi][ni][1]);
            atomicAdd(&g_Otmp[(size_t)(r0+8)*HD + h    ], acc[mi][ni][2]);
            atomicAdd(&g_Otmp[(size_t)(r0+8)*HD + h + 1], acc[mi][ni][3]);
        }
    }
}

// ---------------- K6: bias + relu ----------------
__global__ void k_finish(const float* __restrict__ bm, float* __restrict__ out){
    int i = blockIdx.x * blockDim.x + threadIdx.x;
    if (i < NB*HD){
        float v = g_Otmp[i] + bm[i & (HD-1)];
        out[i] = fmaxf(v, 0.f);
    }
}

// ---------------- launch ----------------
extern "C" void kernel_launch(void* const* d_in, const int* in_sizes, int n_in,
                              void* d_out, int out_size){
    (void)in_sizes; (void)n_in; (void)out_size;
    const float* facts     = (const float*)d_in[0];
    const float* questions = (const float*)d_in[1];
    const float* prevM     = (const float*)d_in[2];
    const float* Wr  = (const float*)d_in[3];
    const float* br  = (const float*)d_in[4];
    const float* Ur  = (const float*)d_in[5];
    const float* bur = (const float*)d_in[6];
    const float* W   = (const float*)d_in[7];
    const float* bw  = (const float*)d_in[8];
    const float* U   = (const float*)d_in[9];
    const float* bu  = (const float*)d_in[10];
    const float* Wz1 = (const float*)d_in[11];
    const float* bz1 = (const float*)d_in[12];
    const float* Wz2 = (const float*)d_in[13];
    // d_in[14] = bz2: softmax shift-invariant, cancels.
    const float* Wm  = (const float*)d_in[15];
    const float* bm  = (const float*)d_in[16];
    float* out = (float*)d_out;

    static int attr_done = 0;
    if (!attr_done){
        cudaFuncSetAttribute(k3_G,    cudaFuncAttributeMaxDynamicSharedMemorySize, GEMM_SMEM);
        cudaFuncSetAttribute(k3_F,    cudaFuncAttributeMaxDynamicSharedMemorySize, GEMM_SMEM);
        cudaFuncSetAttribute(k3_scan, cudaFuncAttributeMaxDynamicSharedMemorySize, SCAN_SMEM);
        attr_done = 1;
    }

    k_init<<<512, 256>>>();
    dim3 gG(8, 128);
    k3_G<<<gG, 256, GEMM_SMEM>>>(facts, questions, prevM, Wz1, bz1, Wz2);
    k_softmax<<<128, 128>>>();
    dim3 gF(8, 128, 2);
    k3_F<<<gF, 256, GEMM_SMEM>>>(facts, Wr, br, W, bw);
    k3_scan<<<NCTA_SCAN, 256, SCAN_SMEM>>>(Ur, bur, U, bu);
    dim3 gO(8, 12);
    k_out<<<gO, 256>>>(prevM, questions, Wm);
    k_finish<<<512, 256>>>(bm, out);
}

// round 5
// speedup vs baseline: 1.2374x; 1.0947x over previous
#include <cuda_runtime.h>
#include <cstdint>
#include <cstddef>

#define HD 1024
#define NB 128
#define NS 128
#define NROW (NB*NS)
#define LDK 36
#define CH (128*36)          // uints per 128x32 tile
#define NCTA_SCAN 128
#define GEMM_SMEM (4*CH*4)   // 73728 B  (A x2, B x2)
#define SCAN_SMEM (8*CH*4)   // 147456 B (A x4 subs, B x4 resident)

// ---------------- scratch ----------------
__device__ __align__(16) float g_FR[(size_t)NS*NB*HD];
__device__ __align__(16) float g_FW[(size_t)NS*NB*HD];
__device__ __align__(16) float    g_C[NB*HD];
__device__ __align__(16) unsigned g_Ctf[NB*HD];
__device__ __align__(16) float g_Otmp[NB*HD];
__device__ __align__(16) float g_part[(size_t)NCTA_SCAN*128*128];
__device__ __align__(16) float g_Glogit[NROW];
__device__ __align__(16) float g_Gt[NS*NB];
// pre-converted tf32 operands
__device__ __align__(16) unsigned g_ftf[(size_t)NB*NS*HD];   // facts, 67MB
__device__ __align__(16) unsigned g_Wz1tf[(size_t)HD*4*HD];  // 16MB
__device__ __align__(16) unsigned g_Wrtf[(size_t)HD*HD];
__device__ __align__(16) unsigned g_Wtf[(size_t)HD*HD];
__device__ __align__(16) unsigned g_flags[NCTA_SCAN];

// ---------------- helpers ----------------
__device__ __forceinline__ unsigned f2tf(float f){
    unsigned u; asm("cvt.rna.tf32.f32 %0, %1;" : "=r"(u) : "f"(f)); return u;
}
__device__ __forceinline__ uint32_t smem_u32(const void* p){
    uint32_t a; asm("{ .reg .u64 t; cvta.to.shared.u64 t, %1; cvt.u32.u64 %0, t; }"
                    : "=r"(a) : "l"(p)); return a;
}
__device__ __forceinline__ void cpa16(uint32_t dst, const void* src){
    asm volatile("cp.async.cg.shared.global [%0], [%1], 16;" :: "r"(dst), "l"(src));
}
#define CP_COMMIT() asm volatile("cp.async.commit_group;" ::: "memory")
#define CP_WAIT(n)  asm volatile("cp.async.wait_group %0;" :: "n"(n) : "memory")

__device__ __forceinline__ unsigned ldcg_u32(const unsigned* p){
    unsigned v; asm volatile("ld.global.cg.u32 %0, [%1];" : "=r"(v) : "l"(p)); return v;
}
__device__ __forceinline__ void stcg_u32(unsigned* p, unsigned v){
    asm volatile("st.global.cg.u32 [%0], %1;" :: "l"(p), "r"(v) : "memory");
}

__device__ __forceinline__ void ldsm4(unsigned* r, uint32_t addr){
    asm volatile("ldmatrix.sync.aligned.m8n8.x4.shared.b16 {%0,%1,%2,%3}, [%4];"
        : "=r"(r[0]),"=r"(r[1]),"=r"(r[2]),"=r"(r[3]) : "r"(addr));
}
__device__ __forceinline__ void mma8(float* d, const unsigned* a, const unsigned* b){
    asm volatile("mma.sync.aligned.m16n8k8.row.col.f32.tf32.tf32.f32 "
        "{%0,%1,%2,%3},{%4,%5,%6,%7},{%8,%9},{%0,%1,%2,%3};\n"
        : "+f"(d[0]),"+f"(d[1]),"+f"(d[2]),"+f"(d[3])
        : "r"(a[0]),"r"(a[1]),"r"(a[2]),"r"(a[3]),"r"(b[0]),"r"(b[1]));
}

// One 128x128x32 tile-step via ldmatrix (all operands already tf32 in SMEM).
__device__ __forceinline__ void compute32(uint32_t aBase, uint32_t bBase,
        uint32_t offA0, uint32_t offA1, const uint32_t* offB, float acc[2][8][4]){
    #pragma unroll
    for (int ks = 0; ks < 4; ks++){
        unsigned a0[4], a1[4], bb[4][4];
        ldsm4(a0, aBase + offA0 + ks*32);
        ldsm4(a1, aBase + offA1 + ks*32);
        #pragma unroll
        for (int p = 0; p < 4; p++) ldsm4(bb[p], bBase + offB[p] + ks*32);
        #pragma unroll
        for (int mi = 0; mi < 2; mi++){
            const unsigned* a = mi ? a1 : a0;
            #pragma unroll
            for (int p = 0; p < 4; p++){
                unsigned b0[2] = {bb[p][0], bb[p][2]};
                unsigned b1[2] = {bb[p][1], bb[p][3]};
                mma8(acc[mi][2*p],   a, b0);
                mma8(acc[mi][2*p+1], a, b1);
            }
        }
    }
}

#define LDSM_OFFSETS() \
    int rowA0 = warp_m + (lane & 7) + ((lane >> 3) & 1)*8; \
    int colw  = ((lane >> 4) & 1)*4; \
    uint32_t offA0 = (uint32_t)(rowA0*LDK + colw)*4; \
    uint32_t offA1 = (uint32_t)((rowA0+16)*LDK + colw)*4; \
    uint32_t offB[4]; \
    _Pragma("unroll") for (int p_ = 0; p_ < 4; p_++) \
        offB[p_] = (uint32_t)((warp_n + p_*16 + (lane & 15))*LDK + colw)*4;

#define ZERO_ACC(acc) { \
    _Pragma("unroll") for (int _i=0;_i<2;_i++) \
    _Pragma("unroll") for (int _j=0;_j<8;_j++) \
    _Pragma("unroll") for (int _k=0;_k<4;_k++) acc[_i][_j][_k]=0.f; }

// ---------------- K0: per-replay init ----------------
__global__ void k_init(){
    int i = blockIdx.x * blockDim.x + threadIdx.x;
    if (i < NCTA_SCAN) g_flags[i] = 0u;
    if (i < NROW) g_Glogit[i] = 0.f;
    if (i < NB*HD){ g_C[i] = 0.f; g_Ctf[i] = 0u; g_Otmp[i] = 0.f; }
}

// ---------------- Kc: fp32 -> tf32 bulk convert ----------------
__global__ void k_cvt(const float4* __restrict__ src, uint4* __restrict__ dst, int n4){
    for (int i = blockIdx.x*blockDim.x + threadIdx.x; i < n4; i += gridDim.x*blockDim.x){
        float4 v = src[i];
        dst[i] = make_uint4(f2tf(v.x), f2tf(v.y), f2tf(v.z), f2tf(v.w));
    }
}

// ================= K1: G logits =================
__global__ void __launch_bounds__(256,2) k4_G(
        const float* __restrict__ facts, const float* __restrict__ q,
        const float* __restrict__ pm,
        const float* __restrict__ bz1, const float* __restrict__ Wz2){
    extern __shared__ unsigned us[];
    uint32_t sbase = smem_u32(us);
    int tid = threadIdx.x, wid = tid >> 5, lane = tid & 31;
    int lg = lane >> 2, lk = lane & 3;
    int warp_m = (wid >> 1) * 32, warp_n = (wid & 1) * 64;
    int nt = blockIdx.x, bt = blockIdx.y;
    int c4v = (tid & 7) * 4, rb = tid >> 3;
    LDSM_OFFSETS();
    const float* fb = facts + (size_t)bt*NS*HD;
    const float* qb = q  + (size_t)bt*HD;
    const float* mb = pm + (size_t)bt*HD;

    float4 pf[4];
    float acc[2][8][4]; ZERO_ACC(acc);

    #define G_LDG(i_) { int fc_ = ((i_)>>2)*32 + c4v; \
        _Pragma("unroll") for (int it = 0; it < 4; it++) \
            pf[it] = *reinterpret_cast<const float4*>(fb + (size_t)(rb + it*32)*HD + fc_); }
    #define G_STS(i_, buf_) { int part_ = (i_) & 3; int fc_ = ((i_)>>2)*32 + c4v; \
        float4 qv_ = *reinterpret_cast<const float4*>(qb + fc_); \
        float4 mv_ = *reinterpret_cast<const float4*>(mb + fc_); \
        _Pragma("unroll") for (int it = 0; it < 4; it++){ \
            float4 f_ = pf[it]; float4 z_; \
            if (part_ == 0){      z_.x=f_.x*qv_.x; z_.y=f_.y*qv_.y; z_.z=f_.z*qv_.z; z_.w=f_.w*qv_.w; } \
            else if (part_ == 1){ z_.x=f_.x*mv_.x; z_.y=f_.y*mv_.y; z_.z=f_.z*mv_.z; z_.w=f_.w*mv_.w; } \
            else if (part_ == 2){ z_.x=fabsf(f_.x-qv_.x); z_.y=fabsf(f_.y-qv_.y); z_.z=fabsf(f_.z-qv_.z); z_.w=fabsf(f_.w-qv_.w); } \
            else {               z_.x=fabsf(f_.x-mv_.x); z_.y=fabsf(f_.y-mv_.y); z_.z=fabsf(f_.z-mv_.z); z_.w=fabsf(f_.w-mv_.w); } \
            unsigned* d_ = us + (buf_)*CH + (rb + it*32)*LDK + c4v; \
            d_[0]=f2tf(z_.x); d_[1]=f2tf(z_.y); d_[2]=f2tf(z_.z); d_[3]=f2tf(z_.w); } }
    #define G_CPB(i_, buf_) { int part_ = (i_) & 3; int fc_ = ((i_)>>2)*32; \
        _Pragma("unroll") for (int j = 0; j < 4; j++){ int n_ = rb + j*32; \
            cpa16(sbase + ((2 + (buf_))*CH + n_*LDK + c4v)*4, \
                  g_Wz1tf + (size_t)(nt*128 + n_)*(4*HD) + part_*HD + fc_ + c4v); } CP_COMMIT(); }

    G_LDG(0); G_CPB(0, 0);
    const int NBLK = 128;
    for (int i = 0; i < NBLK; i++){
        int buf = i & 1;
        G_STS(i, buf);
        if (((i+1) & 3) == 0 && i+1 < NBLK) G_LDG(i+1);
        CP_WAIT(0);
        __syncthreads();
        if (i+1 < NBLK) G_CPB(i+1, buf^1);
        compute32(sbase + buf*CH*4, sbase + (2+buf)*CH*4, offA0, offA1, offB, acc);
    }

    float rs[4] = {0.f, 0.f, 0.f, 0.f};
    #pragma unroll
    for (int mi = 0; mi < 2; mi++)
        #pragma unroll
        for (int ni = 0; ni < 8; ni++){
            int c0 = nt*128 + warp_n + ni*8 + lk*2;
            float w0 = Wz2[c0], w1 = Wz2[c0+1];
            float z0 = bz1[c0], z1 = bz1[c0+1];
            rs[mi*2+0] += tanhf(acc[mi][ni][0]+z0)*w0 + tanhf(acc[mi][ni][1]+z1)*w1;
            rs[mi*2+1] += tanhf(acc[mi][ni][2]+z0)*w0 + tanhf(acc[mi][ni][3]+z1)*w1;
        }
    #pragma unroll
    for (int r = 0; r < 4; r++){
        rs[r] += __shfl_xor_sync(0xffffffffu, rs[r], 1);
        rs[r] += __shfl_xor_sync(0xffffffffu, rs[r], 2);
    }
    if (lk == 0){
        int s0 = warp_m + lg;
        atomicAdd(&g_Glogit[bt*NS + s0     ], rs[0]);
        atomicAdd(&g_Glogit[bt*NS + s0 + 8 ], rs[1]);
        atomicAdd(&g_Glogit[bt*NS + s0 + 16], rs[2]);
        atomicAdd(&g_Glogit[bt*NS + s0 + 24], rs[3]);
    }
}

// ================= K3: FR/FW (pure cp.async both operands) =================
__global__ void __launch_bounds__(256,2) k4_F(
        const float* __restrict__ br, const float* __restrict__ bw){
    extern __shared__ unsigned us[];
    uint32_t sbase = smem_u32(us);
    int tid = threadIdx.x, wid = tid >> 5, lane = tid & 31;
    int lg = lane >> 2, lk = lane & 3;
    int warp_m = (wid >> 1) * 32, warp_n = (wid & 1) * 64;
    int nt = blockIdx.x, bt = blockIdx.y, which = blockIdx.z;
    const unsigned* Wtf  = which ? g_Wtf : g_Wrtf;
    const float*    bsel = which ? bw : br;
    float* Out = which ? g_FW : g_FR;
    int c4v = (tid & 7) * 4, rb = tid >> 3;
    LDSM_OFFSETS();
    const unsigned* fb = g_ftf + (size_t)bt*NS*HD;
    float acc[2][8][4]; ZERO_ACC(acc);

    #define F_CP(i_, buf_) { \
        _Pragma("unroll") for (int j = 0; j < 4; j++){ int r_ = rb + j*32; \
            cpa16(sbase + ((buf_)*CH + r_*LDK + c4v)*4, \
                  fb + (size_t)r_*HD + (i_)*32 + c4v); \
            cpa16(sbase + ((2 + (buf_))*CH + r_*LDK + c4v)*4, \
                  Wtf + (size_t)(nt*128 + r_)*HD + (i_)*32 + c4v); } CP_COMMIT(); }

    F_CP(0, 0);
    const int NBLK = 32;
    for (int i = 0; i < NBLK; i++){
        int buf = i & 1;
        CP_WAIT(0);
        __syncthreads();
        if (i+1 < NBLK) F_CP(i+1, buf^1);
        compute32(sbase + buf*CH*4, sbase + (2+buf)*CH*4, offA0, offA1, offB, acc);
    }

    #pragma unroll
    for (int mi = 0; mi < 2; mi++){
        int r0 = warp_m + mi*16 + lg;   // s index
        #pragma unroll
        for (int ni = 0; ni < 8; ni++){
            int h = nt*128 + warp_n + ni*8 + lk*2;
            float b0 = bsel[h], b1 = bsel[h+1];
            float2 v0 = make_float2(acc[mi][ni][0]+b0, acc[mi][ni][1]+b1);
            float2 v1 = make_float2(acc[mi][ni][2]+b0, acc[mi][ni][3]+b1);
            *reinterpret_cast<float2*>(Out + (size_t)r0*(NB*HD) + (size_t)bt*HD + h) = v0;
            *reinterpret_cast<float2*>(Out + (size_t)(r0+8)*(NB*HD) + (size_t)bt*HD + h) = v1;
        }
    }
}

// ---------------- K2: softmax ----------------
__global__ void k_softmax(){
    int bt = blockIdx.x, t = threadIdx.x;
    float v = g_Glogit[bt*NS + t];
    __shared__ float sm_[4], ss[4];
    float mx = v;
    #pragma unroll
    for (int o = 16; o; o >>= 1) mx = fmaxf(mx, __shfl_xor_sync(0xffffffffu, mx, o));
    if ((t & 31) == 0) sm_[t >> 5] = mx;
    __syncthreads();
    mx = fmaxf(fmaxf(sm_[0], sm_[1]), fmaxf(sm_[2], sm_[3]));
    float e = __expf(v - mx);
    float sum = e;
    #pragma unroll
    for (int o = 16; o; o >>= 1) sum += __shfl_xor_sync(0xffffffffu, sum, o);
    if ((t & 31) == 0) ss[t >> 5] = sum;
    __syncthreads();
    sum = ss[0] + ss[1] + ss[2] + ss[3];
    g_Gt[t*NB + bt] = e / sum;
}

// ---------------- K4: persistent scan ----------------
__device__ __forceinline__ void gsync(unsigned step, int tid, int cta){
    __syncthreads();
    if (tid == 0){
        __threadfence();
        stcg_u32(&g_flags[cta], step);
    }
    if (tid < NCTA_SCAN){
        while (ldcg_u32(&g_flags[tid]) < step) { }
    }
    __threadfence();
    __syncthreads();
}
__device__ __forceinline__ float gru_upd(float fr, float fw, float y1, float y2,
                                         float b_ur, float b_u, float c, float g){
    float r  = 1.f / (1.f + __expf(-(fr + y1 + b_ur)));
    float ht = tanhf(fw + r * (y2 + b_u));
    return g * ht + (1.f - g) * c;
}

__global__ void __launch_bounds__(256,1) k4_scan(
        const float* __restrict__ Ur, const float* __restrict__ bur,
        const float* __restrict__ U,  const float* __restrict__ bu){
    extern __shared__ unsigned us[];   // A subs: [0,4CH); B resident tf32: [4CH,8CH)
    uint32_t sbase = smem_u32(us);
    int cta = blockIdx.x, tid = threadIdx.x;
    int wid = tid >> 5, lane = tid & 31, lg = lane >> 2, lk = lane & 3;
    int warp_m = (wid >> 1) * 32, warp_n = (wid & 1) * 64;
    int c4v = (tid & 7) * 4, rb = tid >> 3;
    LDSM_OFFSETS();
    int nt = cta >> 3;              // 0..15: 0-7 -> Y1 (Ur), 8-15 -> Y2 (U)
    int kcb = (cta & 7) * 128;      // K slice
    const float* Wsel = (nt < 8) ? Ur : U;
    int nbase = (nt & 7) * 128;
    float* P = g_part + (size_t)cta * 16384;

    // weights resident, tf32, all 128 steps
    #pragma unroll
    for (int j = 0; j < 16; j++){
        int s = j >> 2, n = rb + (j & 3)*32;
        float4 v = *reinterpret_cast<const float4*>(Wsel + (size_t)(nbase+n)*HD + kcb + s*32 + c4v);
        unsigned* d = us + 4*CH + s*CH + n*LDK + c4v;
        d[0]=f2tf(v.x); d[1]=f2tf(v.y); d[2]=f2tf(v.z); d[3]=f2tf(v.w);
    }
    __syncthreads();

    int e  = (cta*256 + tid) * 4;
    int eb = e >> 10, eh = e & (HD-1);
    int nt1 = eh >> 7, hm = eh & 127;
    // hoisted invariants
    float4 vur = *reinterpret_cast<const float4*>(bur + eh);
    float4 vu  = *reinterpret_cast<const float4*>(bu + eh);

    unsigned bar = 0;
    for (int s = 0; s < NS; s++){
        // prefetch phase-B inputs (independent of phase A)
        float4 fr = *reinterpret_cast<const float4*>(g_FR + (size_t)s*NB*HD + (size_t)eb*HD + eh);
        float4 fw = *reinterpret_cast<const float4*>(g_FW + (size_t)s*NB*HD + (size_t)eb*HD + eh);
        float4 co = __ldcg(reinterpret_cast<const float4*>(g_C + (size_t)eb*HD + eh));
        float gg = g_Gt[s*NB + eb];

        // ---- phase A: cp.async pre-converted C slice (4 groups), ldmatrix compute
        #pragma unroll
        for (int sg = 0; sg < 4; sg++){
            #pragma unroll
            for (int j = 0; j < 4; j++){
                int r = rb + j*32;
                cpa16(sbase + (sg*CH + r*LDK + c4v)*4,
                      g_Ctf + (size_t)r*HD + kcb + sg*32 + c4v);
            }
            CP_COMMIT();
        }
        float acc[2][8][4]; ZERO_ACC(acc);
        #pragma unroll
        for (int sub = 0; sub < 4; sub++){
            if (sub == 0)      CP_WAIT(3);
            else if (sub == 1) CP_WAIT(2);
            else if (sub == 2) CP_WAIT(1);
            else               CP_WAIT(0);
            __syncthreads();
            compute32(sbase + sub*CH*4, sbase + (4+sub)*CH*4, offA0, offA1, offB, acc);
        }
        #pragma unroll
        for (int mi = 0; mi < 2; mi++){
            int r0 = warp_m + mi*16 + lg;
            #pragma unroll
            for (int ni = 0; ni < 8; ni++){
                int c = warp_n + ni*8 + lk*2;
                __stcg(reinterpret_cast<float2*>(P + r0*128 + c),
                       make_float2(acc[mi][ni][0], acc[mi][ni][1]));
                __stcg(reinterpret_cast<float2*>(P + (r0+8)*128 + c),
                       make_float2(acc[mi][ni][2], acc[mi][ni][3]));
            }
        }
        gsync(++bar, tid, cta);

        // ---- phase B: reduce partials, GRU update, write C (raw + tf32)
        float4 y1 = make_float4(0,0,0,0), y2 = make_float4(0,0,0,0);
        #pragma unroll
        for (int kk = 0; kk < 8; kk++){
            float4 p1 = __ldcg(reinterpret_cast<const float4*>(
                g_part + (size_t)(nt1*8 + kk)*16384 + eb*128 + hm));
            float4 p2 = __ldcg(reinterpret_cast<const float4*>(
                g_part + (size_t)((nt1+8)*8 + kk)*16384 + eb*128 + hm));
            y1.x += p1.x; y1.y += p1.y; y1.z += p1.z; y1.w += p1.w;
            y2.x += p2.x; y2.y += p2.y; y2.z += p2.z; y2.w += p2.w;
        }
        float4 cn;
        cn.x = gru_upd(fr.x, fw.x, y1.x, y2.x, vur.x, vu.x, co.x, gg);
        cn.y = gru_upd(fr.y, fw.y, y1.y, y2.y, vur.y, vu.y, co.y, gg);
        cn.z = gru_upd(fr.z, fw.z, y1.z, y2.z, vur.z, vu.z, co.z, gg);
        cn.w = gru_upd(fr.w, fw.w, y1.w, y2.w, vur.w, vu.w, co.w, gg);
        __stcg(reinterpret_cast<float4*>(g_C + (size_t)eb*HD + eh), cn);
        uint4 ct;
        ct.x = f2tf(cn.x); ct.y = f2tf(cn.y); ct.z = f2tf(cn.z); ct.w = f2tf(cn.w);
        __stcg(reinterpret_cast<uint4*>(g_Ctf + (size_t)eb*HD + eh), ct);
        gsync(++bar, tid, cta);
    }
}

// ---------------- K5: final GEMM (legacy, small) ----------------
__device__ __forceinline__ void compute_chunk(const unsigned* As, const unsigned* Bs,
        float acc[2][8][4], int warp_m, int warp_n, int lg, int lk){
    #pragma unroll
    for (int ks = 0; ks < 4; ks++){
        int k0 = ks*8 + lk;
        unsigned a[2][4], b[8][2];
        #pragma unroll
        for (int mi = 0; mi < 2; mi++){
            int m0 = warp_m + mi*16 + lg;
            a[mi][0] = As[m0*LDK + k0];
            a[mi][1] = As[(m0+8)*LDK + k0];
            a[mi][2] = As[m0*LDK + k0+4];
            a[mi][3] = As[(m0+8)*LDK + k0+4];
        }
        #pragma unroll
        for (int ni = 0; ni < 8; ni++){
            int n0 = warp_n + ni*8 + lg;
            b[ni][0] = Bs[n0*LDK + k0];
            b[ni][1] = Bs[n0*LDK + k0+4];
        }
        #pragma unroll
        for (int mi = 0; mi < 2; mi++)
            #pragma unroll
            for (int ni = 0; ni < 8; ni++)
                mma8(acc[mi][ni], a[mi], b[ni]);
    }
}
__global__ void k_out(const float* __restrict__ pm, const float* __restrict__ q,
                      const float* __restrict__ Wm){
    __shared__ unsigned As[128*LDK];
    __shared__ unsigned Bs[128*LDK];
    int nt = blockIdx.x;
    int ks = blockIdx.y;
    int kbase = ks * 256;
    int tid = threadIdx.x, wid = tid >> 5, lane = tid & 31, lg = lane >> 2, lk = lane & 3;
    int warp_m = (wid >> 1) * 32, warp_n = (wid & 1) * 64;
    float acc[2][8][4]; ZERO_ACC(acc);

    for (int kc = 0; kc < 256; kc += 32){
        int kg = kbase + kc;
        int seg = kg >> 10;
        int jj = kg & (HD-1);
        #pragma unroll
        for (int i = 0; i < 4; i++){
            int slot = tid + i*256;
            int bb = slot >> 3, c4 = (slot & 7) * 4;
            float4 v;
            if (seg == 0)      v = *reinterpret_cast<const float4*>(pm + (size_t)bb*HD + jj + c4);
            else if (seg == 1) v = __ldcg(reinterpret_cast<const float4*>(g_C + (size_t)bb*HD + jj + c4));
            else               v = *reinterpret_cast<const float4*>(q + (size_t)bb*HD + jj + c4);
            As[bb*LDK + c4+0] = f2tf(v.x);
            As[bb*LDK + c4+1] = f2tf(v.y);
            As[bb*LDK + c4+2] = f2tf(v.z);
            As[bb*LDK + c4+3] = f2tf(v.w);
        }
        #pragma unroll
        for (int i = 0; i < 4; i++){
            int slot = tid + i*256;
            int n = slot >> 3, c4 = (slot & 7) * 4;
            float4 v = *reinterpret_cast<const float4*>(Wm + (size_t)(nt*128+n)*(3*HD) + kg + c4);
            Bs[n*LDK + c4+0] = f2tf(v.x);
            Bs[n*LDK + c4+1] = f2tf(v.y);
            Bs[n*LDK + c4+2] = f2tf(v.z);
            Bs[n*LDK + c4+3] = f2tf(v.w);
        }
        __syncthreads();
        compute_chunk(As, Bs, acc, warp_m, warp_n, lg, lk);
        __syncthreads();
    }
    #pragma unroll
    for (int mi = 0; mi < 2; mi++){
        int r0 = warp_m + mi*16 + lg;
        #pragma unroll
        for (int ni = 0; ni < 8; ni++){
            int h = nt*128 + warp_n + ni*8 + lk*2;
            atomicAdd(&g_Otmp[(size_t)r0*HD + h     ], acc[mi][ni][0]);
            atomicAdd(&g_Otmp[(size_t)r0*HD + h + 1 ], acc[mi][ni][1]);
            atomicAdd(&g_Otmp[(size_t)(r0+8)*HD + h    ], acc[mi][ni][2]);
            atomicAdd(&g_Otmp[(size_t)(r0+8)*HD + h + 1], acc[mi][ni][3]);
        }
    }
}

// ---------------- K6: bias + relu ----------------
__global__ void k_finish(const float* __restrict__ bm, float* __restrict__ out){
    int i = blockIdx.x * blockDim.x + threadIdx.x;
    if (i < NB*HD){
        float v = g_Otmp[i] + bm[i & (HD-1)];
        out[i] = fmaxf(v, 0.f);
    }
}

// ---------------- launch ----------------
extern "C" void kernel_launch(void* const* d_in, const int* in_sizes, int n_in,
                              void* d_out, int out_size){
    (void)in_sizes; (void)n_in; (void)out_size;
    const float* facts     = (const float*)d_in[0];
    const float* questions = (const float*)d_in[1];
    const float* prevM     = (const float*)d_in[2];
    const float* Wr  = (const float*)d_in[3];
    const float* br  = (const float*)d_in[4];
    const float* Ur  = (const float*)d_in[5];
    const float* bur = (const float*)d_in[6];
    const float* W   = (const float*)d_in[7];
    const float* bw  = (const float*)d_in[8];
    const float* U   = (const float*)d_in[9];
    const float* bu  = (const float*)d_in[10];
    const float* Wz1 = (const float*)d_in[11];
    const float* bz1 = (const float*)d_in[12];
    const float* Wz2 = (const float*)d_in[13];
    // d_in[14] = bz2: softmax shift-invariant, cancels.
    const float* Wm  = (const float*)d_in[15];
    const float* bm  = (const float*)d_in[16];
    float* out = (float*)d_out;

    static int attr_done = 0;
    if (!attr_done){
        cudaFuncSetAttribute(k4_G,    cudaFuncAttributeMaxDynamicSharedMemorySize, GEMM_SMEM);
        cudaFuncSetAttribute(k4_F,    cudaFuncAttributeMaxDynamicSharedMemorySize, GEMM_SMEM);
        cudaFuncSetAttribute(k4_scan, cudaFuncAttributeMaxDynamicSharedMemorySize, SCAN_SMEM);
        attr_done = 1;
    }

    unsigned* dWz1tf; cudaGetSymbolAddress((void**)&dWz1tf, g_Wz1tf);
    unsigned* dWrtf;  cudaGetSymbolAddress((void**)&dWrtf,  g_Wrtf);
    unsigned* dWtf;   cudaGetSymbolAddress((void**)&dWtf,   g_Wtf);
    unsigned* dftf;   cudaGetSymbolAddress((void**)&dftf,   g_ftf);

    k_init<<<512, 256>>>();
    k_cvt<<<2048, 256>>>((const float4*)facts, (uint4*)dftf,   (NB*NS*HD)/4);
    k_cvt<<<1024, 256>>>((const float4*)Wz1,   (uint4*)dWz1tf, (HD*4*HD)/4);
    k_cvt<<<512, 256>>>((const float4*)Wr,     (uint4*)dWrtf,  (HD*HD)/4);
    k_cvt<<<512, 256>>>((const float4*)W,      (uint4*)dWtf,   (HD*HD)/4);
    dim3 gG(8, 128);
    k4_G<<<gG, 256, GEMM_SMEM>>>(facts, questions, prevM, bz1, Wz2);
    k_softmax<<<128, 128>>>();
    dim3 gF(8, 128, 2);
    k4_F<<<gF, 256, GEMM_SMEM>>>(br, bw);
    k4_scan<<<NCTA_SCAN, 256, SCAN_SMEM>>>(Ur, bur, U, bu);
    dim3 gO(8, 12);
    k_out<<<gO, 256>>>(prevM, questions, Wm);
    k_finish<<<512, 256>>>(bm, out);
}

// round 6
// speedup vs baseline: 1.3759x; 1.1119x over previous
#include <cuda_runtime.h>
#include <cstdint>
#include <cstddef>

#define HD 1024
#define NB 128
#define NS 128
#define NROW (NB*NS)
#define LDK 36
#define NCTA_SCAN 128
#define TILE_B 16384            // bytes per 128x32 swizzled tf32 tile
#define GEMM_SMEM (6*TILE_B)    // 98304: 3xA + 3xB
#define SCAN_SMEM (8*TILE_B)    // 131072: 4xA subs + 4xB resident

// ---------------- scratch ----------------
__device__ __align__(16) float g_FR[(size_t)NS*NB*HD];
__device__ __align__(16) float g_FW[(size_t)NS*NB*HD];
__device__ __align__(16) float    g_C[NB*HD];
__device__ __align__(16) unsigned g_Ctf[NB*HD];
__device__ __align__(16) float g_Otmp[NB*HD];
__device__ __align__(16) float g_part[(size_t)NCTA_SCAN*128*128];
__device__ __align__(16) float g_Glogit[NROW];
__device__ __align__(16) float g_Gt[NS*NB];
// pre-converted tf32 operands
__device__ __align__(16) unsigned g_ftf[(size_t)NB*NS*HD];     // facts
__device__ __align__(16) unsigned g_ztf[(size_t)NROW*4*HD];    // z, 268MB
__device__ __align__(16) unsigned g_Wz1tf[(size_t)HD*4*HD];
__device__ __align__(16) unsigned g_Wrtf[(size_t)HD*HD];
__device__ __align__(16) unsigned g_Wtf[(size_t)HD*HD];
__device__ __align__(16) unsigned g_flags[NCTA_SCAN*32];       // 1 line / CTA

// ---------------- helpers ----------------
__device__ __forceinline__ unsigned f2tf(float f){
    unsigned u; asm("cvt.rna.tf32.f32 %0, %1;" : "=r"(u) : "f"(f)); return u;
}
__device__ __forceinline__ uint32_t smem_u32(const void* p){
    uint32_t a; asm("{ .reg .u64 t; cvta.to.shared.u64 t, %1; cvt.u32.u64 %0, t; }"
                    : "=r"(a) : "l"(p)); return a;
}
__device__ __forceinline__ void cpa16(uint32_t dst, const void* src){
    asm volatile("cp.async.cg.shared.global [%0], [%1], 16;" :: "r"(dst), "l"(src));
}
#define CP_COMMIT() asm volatile("cp.async.commit_group;" ::: "memory")
#define CP_WAIT(n)  asm volatile("cp.async.wait_group %0;" :: "n"(n) : "memory")

__device__ __forceinline__ unsigned ldcg_u32(const unsigned* p){
    unsigned v; asm volatile("ld.global.cg.u32 %0, [%1];" : "=r"(v) : "l"(p)); return v;
}
__device__ __forceinline__ void stcg_u32(unsigned* p, unsigned v){
    asm volatile("st.global.cg.u32 [%0], %1;" :: "l"(p), "r"(v) : "memory");
}
__device__ __forceinline__ void ldsm4(unsigned* r, uint32_t addr){
    asm volatile("ldmatrix.sync.aligned.m8n8.x4.shared.b16 {%0,%1,%2,%3}, [%4];"
        : "=r"(r[0]),"=r"(r[1]),"=r"(r[2]),"=r"(r[3]) : "r"(addr));
}
__device__ __forceinline__ void mma8(float* d, const unsigned* a, const unsigned* b){
    asm volatile("mma.sync.aligned.m16n8k8.row.col.f32.tf32.tf32.f32 "
        "{%0,%1,%2,%3},{%4,%5,%6,%7},{%8,%9},{%0,%1,%2,%3};\n"
        : "+f"(d[0]),"+f"(d[1]),"+f"(d[2]),"+f"(d[3])
        : "r"(a[0]),"r"(a[1]),"r"(a[2]),"r"(a[3]),"r"(b[0]),"r"(b[1]));
}

// swizzled tile: offset(row r, 16B-unit u) = r*128 + ((u ^ (r&7))*16)
// All ldmatrix row formulas are == lane&7 (mod 8), so the xor term is
// T[ks] = ((ks*2 + (lane>>4)) ^ (lane&7))*16, shared by all 6 ldsm of a thread.
__device__ __forceinline__ void compute32s(uint32_t aBase, uint32_t bBase,
        const uint32_t* RA, const uint32_t* RB, const uint32_t* T, float acc[2][8][4]){
    #pragma unroll
    for (int ks = 0; ks < 4; ks++){
        unsigned a0[4], a1[4], bb[4][4];
        ldsm4(a0, aBase + RA[0] + T[ks]);
        ldsm4(a1, aBase + RA[1] + T[ks]);
        #pragma unroll
        for (int p = 0; p < 4; p++) ldsm4(bb[p], bBase + RB[p] + T[ks]);
        #pragma unroll
        for (int mi = 0; mi < 2; mi++){
            const unsigned* a = mi ? a1 : a0;
            #pragma unroll
            for (int p = 0; p < 4; p++){
                unsigned b0[2] = {bb[p][0], bb[p][2]};
                unsigned b1[2] = {bb[p][1], bb[p][3]};
                mma8(acc[mi][2*p],   a, b0);
                mma8(acc[mi][2*p+1], a, b1);
            }
        }
    }
}

#define LDSM_OFFSETS() \
    int swl = lane & 7, hlf = (lane >> 4) & 1; \
    int rowA0 = warp_m + (lane & 7) + ((lane >> 3) & 1)*8; \
    uint32_t RA[2] = { (uint32_t)rowA0*128u, (uint32_t)(rowA0+16)*128u }; \
    uint32_t RB[4]; \
    _Pragma("unroll") for (int p_ = 0; p_ < 4; p_++) \
        RB[p_] = (uint32_t)(warp_n + p_*16 + (lane & 15))*128u; \
    uint32_t T[4]; \
    _Pragma("unroll") for (int k_ = 0; k_ < 4; k_++) \
        T[k_] = (uint32_t)(((k_*2 + hlf) ^ swl)*16);

#define ZERO_ACC(acc) { \
    _Pragma("unroll") for (int _i=0;_i<2;_i++) \
    _Pragma("unroll") for (int _j=0;_j<8;_j++) \
    _Pragma("unroll") for (int _k=0;_k<4;_k++) acc[_i][_j][_k]=0.f; }

// loader: thread writes 16B units (row rb+j*32, unit tid&7); swz const per thread
#define GEMM_CP(i_, st_, Abase_, Alds_, Bbase_, Blds_) { \
    int kc_ = (i_)*32; \
    _Pragma("unroll") for (int j = 0; j < 4; j++){ int r_ = rb + j*32; \
        cpa16(sbase + (st_)*TILE_B + r_*128 + swz16, \
              (Abase_) + (size_t)r_*(Alds_) + kc_ + c4v); \
        cpa16(sbase + (3 + (st_))*TILE_B + r_*128 + swz16, \
              (Bbase_) + (size_t)r_*(Blds_) + kc_ + c4v); } CP_COMMIT(); }

// ---------------- K0: per-replay init ----------------
__global__ void k_init(){
    int i = blockIdx.x * blockDim.x + threadIdx.x;
    if (i < NCTA_SCAN*32) g_flags[i] = 0u;
    if (i < NROW) g_Glogit[i] = 0.f;
    if (i < NB*HD){ g_C[i] = 0.f; g_Ctf[i] = 0u; g_Otmp[i] = 0.f; }
}

// ---------------- Kc: fp32 -> tf32 bulk convert ----------------
__global__ void k_cvt(const float4* __restrict__ src, uint4* __restrict__ dst, int n4){
    for (int i = blockIdx.x*blockDim.x + threadIdx.x; i < n4; i += gridDim.x*blockDim.x){
        float4 v = src[i];
        dst[i] = make_uint4(f2tf(v.x), f2tf(v.y), f2tf(v.z), f2tf(v.w));
    }
}

// ---------------- Kz: build z (tf32) ----------------
__global__ void k_zb(const float* __restrict__ facts, const float* __restrict__ q,
                     const float* __restrict__ pm){
    int row = blockIdx.x;           // bt*NS + s
    int bt = row >> 7;
    int t = threadIdx.x;            // 256 -> one float4 of the 1024-wide row
    float4 f  = *reinterpret_cast<const float4*>(facts + (size_t)row*HD + t*4);
    float4 qv = *reinterpret_cast<const float4*>(q  + (size_t)bt*HD + t*4);
    float4 mv = *reinterpret_cast<const float4*>(pm + (size_t)bt*HD + t*4);
    unsigned* zr = g_ztf + (size_t)row*(4*HD);
    uint4 o;
    o = make_uint4(f2tf(f.x*qv.x), f2tf(f.y*qv.y), f2tf(f.z*qv.z), f2tf(f.w*qv.w));
    *reinterpret_cast<uint4*>(zr + 0*HD + t*4) = o;
    o = make_uint4(f2tf(f.x*mv.x), f2tf(f.y*mv.y), f2tf(f.z*mv.z), f2tf(f.w*mv.w));
    *reinterpret_cast<uint4*>(zr + 1*HD + t*4) = o;
    o = make_uint4(f2tf(fabsf(f.x-qv.x)), f2tf(fabsf(f.y-qv.y)), f2tf(fabsf(f.z-qv.z)), f2tf(fabsf(f.w-qv.w)));
    *reinterpret_cast<uint4*>(zr + 2*HD + t*4) = o;
    o = make_uint4(f2tf(fabsf(f.x-mv.x)), f2tf(fabsf(f.y-mv.y)), f2tf(fabsf(f.z-mv.z)), f2tf(fabsf(f.w-mv.w)));
    *reinterpret_cast<uint4*>(zr + 3*HD + t*4) = o;
}

// ================= K1: G logits (pure GEMM over precomputed z) =================
__global__ void __launch_bounds__(256,2) k5_G(
        const float* __restrict__ bz1, const float* __restrict__ Wz2){
    extern __shared__ unsigned us[];
    uint32_t sbase = smem_u32(us);
    int tid = threadIdx.x, wid = tid >> 5, lane = tid & 31;
    int lg = lane >> 2, lk = lane & 3;
    int warp_m = (wid >> 1) * 32, warp_n = (wid & 1) * 64;
    int nt = blockIdx.x, bt = blockIdx.y;
    int c4v = (tid & 7) * 4, rb = tid >> 3;
    uint32_t swz16 = (uint32_t)(((tid & 7) ^ (rb & 7)) * 16);
    LDSM_OFFSETS();
    const unsigned* Ab = g_ztf + (size_t)bt*NS*(4*HD);
    const unsigned* Bb = g_Wz1tf + (size_t)(nt*128)*(4*HD);
    float acc[2][8][4]; ZERO_ACC(acc);

    const int NBLK = 128;
    GEMM_CP(0, 0, Ab, 4*HD, Bb, 4*HD);
    GEMM_CP(1, 1, Ab, 4*HD, Bb, 4*HD);
    int st = 0;
    for (int i = 0; i < NBLK; i++){
        CP_WAIT(1);
        __syncthreads();
        if (i + 2 < NBLK){
            int st2 = st + 2; if (st2 >= 3) st2 -= 3;
            GEMM_CP(i+2, st2, Ab, 4*HD, Bb, 4*HD);
        }
        compute32s(sbase + st*TILE_B, sbase + (3+st)*TILE_B, RA, RB, T, acc);
        if (++st == 3) st = 0;
    }

    float rs[4] = {0.f, 0.f, 0.f, 0.f};
    #pragma unroll
    for (int mi = 0; mi < 2; mi++)
        #pragma unroll
        for (int ni = 0; ni < 8; ni++){
            int c0 = nt*128 + warp_n + ni*8 + lk*2;
            float w0 = Wz2[c0], w1 = Wz2[c0+1];
            float z0 = bz1[c0], z1 = bz1[c0+1];
            rs[mi*2+0] += tanhf(acc[mi][ni][0]+z0)*w0 + tanhf(acc[mi][ni][1]+z1)*w1;
            rs[mi*2+1] += tanhf(acc[mi][ni][2]+z0)*w0 + tanhf(acc[mi][ni][3]+z1)*w1;
        }
    #pragma unroll
    for (int r = 0; r < 4; r++){
        rs[r] += __shfl_xor_sync(0xffffffffu, rs[r], 1);
        rs[r] += __shfl_xor_sync(0xffffffffu, rs[r], 2);
    }
    if (lk == 0){
        int s0 = warp_m + lg;
        atomicAdd(&g_Glogit[bt*NS + s0     ], rs[0]);
        atomicAdd(&g_Glogit[bt*NS + s0 + 8 ], rs[1]);
        atomicAdd(&g_Glogit[bt*NS + s0 + 16], rs[2]);
        atomicAdd(&g_Glogit[bt*NS + s0 + 24], rs[3]);
    }
}

// ================= K3: FR/FW =================
__global__ void __launch_bounds__(256,2) k5_F(
        const float* __restrict__ br, const float* __restrict__ bw){
    extern __shared__ unsigned us[];
    uint32_t sbase = smem_u32(us);
    int tid = threadIdx.x, wid = tid >> 5, lane = tid & 31;
    int lg = lane >> 2, lk = lane & 3;
    int warp_m = (wid >> 1) * 32, warp_n = (wid & 1) * 64;
    int nt = blockIdx.x, bt = blockIdx.y, which = blockIdx.z;
    const unsigned* Wtf  = which ? g_Wtf : g_Wrtf;
    const float*    bsel = which ? bw : br;
    float* Out = which ? g_FW : g_FR;
    int c4v = (tid & 7) * 4, rb = tid >> 3;
    uint32_t swz16 = (uint32_t)(((tid & 7) ^ (rb & 7)) * 16);
    LDSM_OFFSETS();
    const unsigned* Ab = g_ftf + (size_t)bt*NS*HD;
    const unsigned* Bb = Wtf + (size_t)(nt*128)*HD;
    float acc[2][8][4]; ZERO_ACC(acc);

    const int NBLK = 32;
    GEMM_CP(0, 0, Ab, HD, Bb, HD);
    GEMM_CP(1, 1, Ab, HD, Bb, HD);
    int st = 0;
    for (int i = 0; i < NBLK; i++){
        CP_WAIT(1);
        __syncthreads();
        if (i + 2 < NBLK){
            int st2 = st + 2; if (st2 >= 3) st2 -= 3;
            GEMM_CP(i+2, st2, Ab, HD, Bb, HD);
        }
        compute32s(sbase + st*TILE_B, sbase + (3+st)*TILE_B, RA, RB, T, acc);
        if (++st == 3) st = 0;
    }

    #pragma unroll
    for (int mi = 0; mi < 2; mi++){
        int r0 = warp_m + mi*16 + lg;   // s index
        #pragma unroll
        for (int ni = 0; ni < 8; ni++){
            int h = nt*128 + warp_n + ni*8 + lk*2;
            float b0 = bsel[h], b1 = bsel[h+1];
            float2 v0 = make_float2(acc[mi][ni][0]+b0, acc[mi][ni][1]+b1);
            float2 v1 = make_float2(acc[mi][ni][2]+b0, acc[mi][ni][3]+b1);
            *reinterpret_cast<float2*>(Out + (size_t)r0*(NB*HD) + (size_t)bt*HD + h) = v0;
            *reinterpret_cast<float2*>(Out + (size_t)(r0+8)*(NB*HD) + (size_t)bt*HD + h) = v1;
        }
    }
}

// ---------------- K2: softmax ----------------
__global__ void k_softmax(){
    int bt = blockIdx.x, t = threadIdx.x;
    float v = g_Glogit[bt*NS + t];
    __shared__ float sm_[4], ss[4];
    float mx = v;
    #pragma unroll
    for (int o = 16; o; o >>= 1) mx = fmaxf(mx, __shfl_xor_sync(0xffffffffu, mx, o));
    if ((t & 31) == 0) sm_[t >> 5] = mx;
    __syncthreads();
    mx = fmaxf(fmaxf(sm_[0], sm_[1]), fmaxf(sm_[2], sm_[3]));
    float e = __expf(v - mx);
    float sum = e;
    #pragma unroll
    for (int o = 16; o; o >>= 1) sum += __shfl_xor_sync(0xffffffffu, sum, o);
    if ((t & 31) == 0) ss[t >> 5] = sum;
    __syncthreads();
    sum = ss[0] + ss[1] + ss[2] + ss[3];
    g_Gt[t*NB + bt] = e / sum;
}

// ---------------- K4: persistent scan ----------------
__device__ __forceinline__ void gsync(unsigned step, int tid, int cta){
    __syncthreads();
    if (tid == 0){
        __threadfence();
        stcg_u32(&g_flags[cta*32], step);
    }
    if (tid < NCTA_SCAN){
        while (ldcg_u32(&g_flags[tid*32]) < step) { }
    }
    __threadfence();
    __syncthreads();
}
__device__ __forceinline__ float gru_upd(float fr, float fw, float y1, float y2,
                                         float b_ur, float b_u, float c, float g){
    float r  = 1.f / (1.f + __expf(-(fr + y1 + b_ur)));
    float ht = tanhf(fw + r * (y2 + b_u));
    return g * ht + (1.f - g) * c;
}

__global__ void __launch_bounds__(256,1) k5_scan(
        const float* __restrict__ Ur, const float* __restrict__ bur,
        const float* __restrict__ U,  const float* __restrict__ bu){
    extern __shared__ unsigned us[];   // A subs: tiles 0-3; B resident: tiles 4-7
    uint32_t sbase = smem_u32(us);
    char* sc = reinterpret_cast<char*>(us);
    int cta = blockIdx.x, tid = threadIdx.x;
    int wid = tid >> 5, lane = tid & 31, lg = lane >> 2, lk = lane & 3;
    int warp_m = (wid >> 1) * 32, warp_n = (wid & 1) * 64;
    int c4v = (tid & 7) * 4, rb = tid >> 3;
    uint32_t swz16 = (uint32_t)(((tid & 7) ^ (rb & 7)) * 16);
    LDSM_OFFSETS();
    int nt = cta >> 3;              // 0..15: 0-7 -> Y1 (Ur), 8-15 -> Y2 (U)
    int kcb = (cta & 7) * 128;      // K slice
    const float* Wsel = (nt < 8) ? Ur : U;
    int nbase = (nt & 7) * 128;
    float* P = g_part + (size_t)cta * 16384;

    // resident tf32 weights in swizzled tiles 4..7
    #pragma unroll
    for (int j = 0; j < 16; j++){
        int s = j >> 2, n = rb + (j & 3)*32;
        float4 v = *reinterpret_cast<const float4*>(Wsel + (size_t)(nbase+n)*HD + kcb + s*32 + c4v);
        uint4 o = make_uint4(f2tf(v.x), f2tf(v.y), f2tf(v.z), f2tf(v.w));
        *reinterpret_cast<uint4*>(sc + (4+s)*TILE_B + n*128 + swz16) = o;
    }
    __syncthreads();

    int e  = (cta*256 + tid) * 4;
    int eb = e >> 10, eh = e & (HD-1);
    int nt1 = eh >> 7, hm = eh & 127;
    float4 vur = *reinterpret_cast<const float4*>(bur + eh);
    float4 vu  = *reinterpret_cast<const float4*>(bu + eh);

    unsigned bar = 0;
    for (int s = 0; s < NS; s++){
        float4 fr = *reinterpret_cast<const float4*>(g_FR + (size_t)s*NB*HD + (size_t)eb*HD + eh);
        float4 fw = *reinterpret_cast<const float4*>(g_FW + (size_t)s*NB*HD + (size_t)eb*HD + eh);
        float4 co = __ldcg(reinterpret_cast<const float4*>(g_C + (size_t)eb*HD + eh));
        float gg = g_Gt[s*NB + eb];

        #pragma unroll
        for (int sg = 0; sg < 4; sg++){
            #pragma unroll
            for (int j = 0; j < 4; j++){
                int r = rb + j*32;
                cpa16(sbase + sg*TILE_B + r*128 + swz16,
                      g_Ctf + (size_t)r*HD + kcb + sg*32 + c4v);
            }
            CP_COMMIT();
        }
        float acc[2][8][4]; ZERO_ACC(acc);
        #pragma unroll
        for (int sub = 0; sub < 4; sub++){
            if (sub == 0)      CP_WAIT(3);
            else if (sub == 1) CP_WAIT(2);
            else if (sub == 2) CP_WAIT(1);
            else               CP_WAIT(0);
            __syncthreads();
            compute32s(sbase + sub*TILE_B, sbase + (4+sub)*TILE_B, RA, RB, T, acc);
        }
        #pragma unroll
        for (int mi = 0; mi < 2; mi++){
            int r0 = warp_m + mi*16 + lg;
            #pragma unroll
            for (int ni = 0; ni < 8; ni++){
                int c = warp_n + ni*8 + lk*2;
                __stcg(reinterpret_cast<float2*>(P + r0*128 + c),
                       make_float2(acc[mi][ni][0], acc[mi][ni][1]));
                __stcg(reinterpret_cast<float2*>(P + (r0+8)*128 + c),
                       make_float2(acc[mi][ni][2], acc[mi][ni][3]));
            }
        }
        gsync(++bar, tid, cta);

        float4 y1 = make_float4(0,0,0,0), y2 = make_float4(0,0,0,0);
        #pragma unroll
        for (int kk = 0; kk < 8; kk++){
            float4 p1 = __ldcg(reinterpret_cast<const float4*>(
                g_part + (size_t)(nt1*8 + kk)*16384 + eb*128 + hm));
            float4 p2 = __ldcg(reinterpret_cast<const float4*>(
                g_part + (size_t)((nt1+8)*8 + kk)*16384 + eb*128 + hm));
            y1.x += p1.x; y1.y += p1.y; y1.z += p1.z; y1.w += p1.w;
            y2.x += p2.x; y2.y += p2.y; y2.z += p2.z; y2.w += p2.w;
        }
        float4 cn;
        cn.x = gru_upd(fr.x, fw.x, y1.x, y2.x, vur.x, vu.x, co.x, gg);
        cn.y = gru_upd(fr.y, fw.y, y1.y, y2.y, vur.y, vu.y, co.y, gg);
        cn.z = gru_upd(fr.z, fw.z, y1.z, y2.z, vur.z, vu.z, co.z, gg);
        cn.w = gru_upd(fr.w, fw.w, y1.w, y2.w, vur.w, vu.w, co.w, gg);
        __stcg(reinterpret_cast<float4*>(g_C + (size_t)eb*HD + eh), cn);
        uint4 ct;
        ct.x = f2tf(cn.x); ct.y = f2tf(cn.y); ct.z = f2tf(cn.z); ct.w = f2tf(cn.w);
        __stcg(reinterpret_cast<uint4*>(g_Ctf + (size_t)eb*HD + eh), ct);
        gsync(++bar, tid, cta);
    }
}

// ---------------- K5: final GEMM (legacy, small) ----------------
__device__ __forceinline__ void compute_chunk(const unsigned* As, const unsigned* Bs,
        float acc[2][8][4], int warp_m, int warp_n, int lg, int lk){
    #pragma unroll
    for (int ks = 0; ks < 4; ks++){
        int k0 = ks*8 + lk;
        unsigned a[2][4], b[8][2];
        #pragma unroll
        for (int mi = 0; mi < 2; mi++){
            int m0 = warp_m + mi*16 + lg;
            a[mi][0] = As[m0*LDK + k0];
            a[mi][1] = As[(m0+8)*LDK + k0];
            a[mi][2] = As[m0*LDK + k0+4];
            a[mi][3] = As[(m0+8)*LDK + k0+4];
        }
        #pragma unroll
        for (int ni = 0; ni < 8; ni++){
            int n0 = warp_n + ni*8 + lg;
            b[ni][0] = Bs[n0*LDK + k0];
            b[ni][1] = Bs[n0*LDK + k0+4];
        }
        #pragma unroll
        for (int mi = 0; mi < 2; mi++)
            #pragma unroll
            for (int ni = 0; ni < 8; ni++)
                mma8(acc[mi][ni], a[mi], b[ni]);
    }
}
__global__ void k_out(const float* __restrict__ pm, const float* __restrict__ q,
                      const float* __restrict__ Wm){
    __shared__ unsigned As[128*LDK];
    __shared__ unsigned Bs[128*LDK];
    int nt = blockIdx.x;
    int ks = blockIdx.y;
    int kbase = ks * 256;
    int tid = threadIdx.x, wid = tid >> 5, lane = tid & 31, lg = lane >> 2, lk = lane & 3;
    int warp_m = (wid >> 1) * 32, warp_n = (wid & 1) * 64;
    float acc[2][8][4]; ZERO_ACC(acc);

    for (int kc = 0; kc < 256; kc += 32){
        int kg = kbase + kc;
        int seg = kg >> 10;
        int jj = kg & (HD-1);
        #pragma unroll
        for (int i = 0; i < 4; i++){
            int slot = tid + i*256;
            int bb = slot >> 3, c4 = (slot & 7) * 4;
            float4 v;
            if (seg == 0)      v = *reinterpret_cast<const float4*>(pm + (size_t)bb*HD + jj + c4);
            else if (seg == 1) v = __ldcg(reinterpret_cast<const float4*>(g_C + (size_t)bb*HD + jj + c4));
            else               v = *reinterpret_cast<const float4*>(q + (size_t)bb*HD + jj + c4);
            As[bb*LDK + c4+0] = f2tf(v.x);
            As[bb*LDK + c4+1] = f2tf(v.y);
            As[bb*LDK + c4+2] = f2tf(v.z);
            As[bb*LDK + c4+3] = f2tf(v.w);
        }
        #pragma unroll
        for (int i = 0; i < 4; i++){
            int slot = tid + i*256;
            int n = slot >> 3, c4 = (slot & 7) * 4;
            float4 v = *reinterpret_cast<const float4*>(Wm + (size_t)(nt*128+n)*(3*HD) + kg + c4);
            Bs[n*LDK + c4+0] = f2tf(v.x);
            Bs[n*LDK + c4+1] = f2tf(v.y);
            Bs[n*LDK + c4+2] = f2tf(v.z);
            Bs[n*LDK + c4+3] = f2tf(v.w);
        }
        __syncthreads();
        compute_chunk(As, Bs, acc, warp_m, warp_n, lg, lk);
        __syncthreads();
    }
    #pragma unroll
    for (int mi = 0; mi < 2; mi++){
        int r0 = warp_m + mi*16 + lg;
        #pragma unroll
        for (int ni = 0; ni < 8; ni++){
            int h = nt*128 + warp_n + ni*8 + lk*2;
            atomicAdd(&g_Otmp[(size_t)r0*HD + h     ], acc[mi][ni][0]);
            atomicAdd(&g_Otmp[(size_t)r0*HD + h + 1 ], acc[mi][ni][1]);
            atomicAdd(&g_Otmp[(size_t)(r0+8)*HD + h    ], acc[mi][ni][2]);
            atomicAdd(&g_Otmp[(size_t)(r0+8)*HD + h + 1], acc[mi][ni][3]);
        }
    }
}

// ---------------- K6: bias + relu ----------------
__global__ void k_finish(const float* __restrict__ bm, float* __restrict__ out){
    int i = blockIdx.x * blockDim.x + threadIdx.x;
    if (i < NB*HD){
        float v = g_Otmp[i] + bm[i & (HD-1)];
        out[i] = fmaxf(v, 0.f);
    }
}

// ---------------- launch ----------------
extern "C" void kernel_launch(void* const* d_in, const int* in_sizes, int n_in,
                              void* d_out, int out_size){
    (void)in_sizes; (void)n_in; (void)out_size;
    const float* facts     = (const float*)d_in[0];
    const float* questions = (const float*)d_in[1];
    const float* prevM     = (const float*)d_in[2];
    const float* Wr  = (const float*)d_in[3];
    const float* br  = (const float*)d_in[4];
    const float* Ur  = (const float*)d_in[5];
    const float* bur = (const float*)d_in[6];
    const float* W   = (const float*)d_in[7];
    const float* bw  = (const float*)d_in[8];
    const float* U   = (const float*)d_in[9];
    const float* bu  = (const float*)d_in[10];
    const float* Wz1 = (const float*)d_in[11];
    const float* bz1 = (const float*)d_in[12];
    const float* Wz2 = (const float*)d_in[13];
    // d_in[14] = bz2: softmax shift-invariant, cancels.
    const float* Wm  = (const float*)d_in[15];
    const float* bm  = (const float*)d_in[16];
    float* out = (float*)d_out;

    static int attr_done = 0;
    if (!attr_done){
        cudaFuncSetAttribute(k5_G,    cudaFuncAttributeMaxDynamicSharedMemorySize, GEMM_SMEM);
        cudaFuncSetAttribute(k5_F,    cudaFuncAttributeMaxDynamicSharedMemorySize, GEMM_SMEM);
        cudaFuncSetAttribute(k5_scan, cudaFuncAttributeMaxDynamicSharedMemorySize, SCAN_SMEM);
        attr_done = 1;
    }

    unsigned* dWz1tf; cudaGetSymbolAddress((void**)&dWz1tf, g_Wz1tf);
    unsigned* dWrtf;  cudaGetSymbolAddress((void**)&dWrtf,  g_Wrtf);
    unsigned* dWtf;   cudaGetSymbolAddress((void**)&dWtf,   g_Wtf);
    unsigned* dftf;   cudaGetSymbolAddress((void**)&dftf,   g_ftf);

    k_init<<<512, 256>>>();
    k_cvt<<<2048, 256>>>((const float4*)facts, (uint4*)dftf,   (NB*NS*HD)/4);
    k_cvt<<<1024, 256>>>((const float4*)Wz1,   (uint4*)dWz1tf, (HD*4*HD)/4);
    k_cvt<<<512, 256>>>((const float4*)Wr,     (uint4*)dWrtf,  (HD*HD)/4);
    k_cvt<<<512, 256>>>((const float4*)W,      (uint4*)dWtf,   (HD*HD)/4);
    k_zb<<<NROW, 256>>>(facts, questions, prevM);
    dim3 gG(8, 128);
    k5_G<<<gG, 256, GEMM_SMEM>>>(bz1, Wz2);
    k_softmax<<<128, 128>>>();
    dim3 gF(8, 128, 2);
    k5_F<<<gF, 256, GEMM_SMEM>>>(br, bw);
    k5_scan<<<NCTA_SCAN, 256, SCAN_SMEM>>>(Ur, bur, U, bu);
    dim3 gO(8, 12);
    k_out<<<gO, 256>>>(prevM, questions, Wm);
    k_finish<<<512, 256>>>(bm, out);
}